// round 1
// baseline (speedup 1.0000x reference)
#include <cuda_runtime.h>
#include <math.h>

// ---------------------------------------------------------------------------
// AttentionalGNN: L=18 layers, D=256, H=4 (head dim 64), B=2, N=1024.
// Layout of all activations: [b2][C][N] (row n contiguous), fp32.
// Channel->head mapping (from reshape(b, HD, H, -1)): c = d*4 + h.
// ---------------------------------------------------------------------------

#define BB   2
#define DD   256
#define NN   1024
#define HH   4
#define HDIM 64
#define TEN  (BB*DD*NN)      // 524288 elems = one [2,256,1024] tensor
#define HTEN (BB*512*NN)     // 1048576 elems = one [2,512,1024] tensor

// Scratch (device globals; no allocation anywhere). [stream][b2][C][N]
__device__ float g_q  [2*TEN];
__device__ float g_k  [2*TEN];
__device__ float g_v  [2*TEN];
__device__ float g_msg[2*TEN];
__device__ float g_mm [2*TEN];
__device__ float g_h  [2*HTEN];
__device__ float g_stats[2*512*2];   // per stream, per channel: scale, shift

// ---------------------------------------------------------------------------
// Generic tiled GEMM: out[s][b2][m][n] = sum_k W[m][k]*X[s][b2][k][n] + bias[m]
// Options: K split across two inputs (concat), BN(normalize+relu) applied to
// X elements on load, residual add in epilogue.
// grid = (32 coltiles [b2*16 + ntile], M/64, 2 streams), block = 256.
// ---------------------------------------------------------------------------
struct GemmArgs {
    const float* W;
    const float* bias;
    const float* X0[2];
    const float* X1[2];
    const float* res[2];
    const float* bnp[2];
    float*       out[2];
    int M, K, K0, use_bn;
};

__global__ __launch_bounds__(256) void gemm_kernel(GemmArgs a) {
    __shared__ __align__(16) float As[16][68];
    __shared__ __align__(16) float Bs[16][68];
    const int s  = blockIdx.z;
    const int jt = blockIdx.x;
    const int b2 = jt >> 4;
    const int n0 = (jt & 15) << 6;
    const int m0 = blockIdx.y << 6;
    const int tid = threadIdx.x;
    const int tx = tid & 15, ty = tid >> 4;
    const int K = a.K, K0 = a.K0, M = a.M;
    const float* __restrict__ W   = a.W;
    const float* __restrict__ X0  = a.X0[s];
    const float* __restrict__ X1  = a.X1[s];
    const float* __restrict__ bnp = a.bnp[s];

    float acc[4][4] = {};

    for (int k0 = 0; k0 < K; k0 += 16) {
        #pragma unroll
        for (int e = tid; e < 1024; e += 256) {
            int kk = e & 15, m = e >> 4;
            As[kk][m] = W[(size_t)(m0 + m) * K + (k0 + kk)];
        }
        #pragma unroll
        for (int e = tid; e < 1024; e += 256) {
            int n = e & 63, kk = e >> 6;
            int k = k0 + kk;
            float v;
            if (k < K0) v = X0[((size_t)b2 * K0 + k) * NN + n0 + n];
            else        v = X1[((size_t)b2 * (K - K0) + (k - K0)) * NN + n0 + n];
            if (a.use_bn) {
                float sc = bnp[2 * k], sh = bnp[2 * k + 1];
                v = fmaxf(fmaf(v, sc, sh), 0.f);
            }
            Bs[kk][n] = v;
        }
        __syncthreads();
        #pragma unroll
        for (int kk = 0; kk < 16; kk++) {
            float4 av = *(const float4*)&As[kk][ty * 4];
            float4 bv = *(const float4*)&Bs[kk][tx * 4];
            float ar[4] = {av.x, av.y, av.z, av.w};
            float br[4] = {bv.x, bv.y, bv.z, bv.w};
            #pragma unroll
            for (int i = 0; i < 4; i++)
                #pragma unroll
                for (int j = 0; j < 4; j++)
                    acc[i][j] = fmaf(ar[i], br[j], acc[i][j]);
        }
        __syncthreads();
    }

    const float* resp = a.res[s];
    float* outp = a.out[s];
    #pragma unroll
    for (int i = 0; i < 4; i++) {
        int m = m0 + ty * 4 + i;
        float bb = a.bias[m];
        size_t off = ((size_t)b2 * M + m) * NN + n0 + tx * 4;
        float4 c = make_float4(acc[i][0] + bb, acc[i][1] + bb,
                               acc[i][2] + bb, acc[i][3] + bb);
        if (resp) {
            float4 r = *(const float4*)(resp + off);
            c.x += r.x; c.y += r.y; c.z += r.z; c.w += r.w;
        }
        *(float4*)(outp + off) = c;
    }
}

// ---------------------------------------------------------------------------
// Flash-style attention on scratch buffers g_q/g_k/g_v -> g_msg.
// grid = (16 qtiles, 8 = b2*4+h, 2 streams), block = 256, dyn smem 69632B.
// Channel of (d,h) is d*4+h. SCALE folded into Q load.
// ---------------------------------------------------------------------------
#define ATTN_SMEM (4 * 64 * 68 * 4)

__global__ __launch_bounds__(256) void attn_kernel() {
    extern __shared__ __align__(16) float sm[];
    float (*Qs)[68] = (float(*)[68])(sm);              // [d][q]
    float (*Ks)[68] = (float(*)[68])(sm + 64 * 68);    // [d][k]
    float (*Vs)[68] = (float(*)[68])(sm + 2 * 64 * 68);// [k][d]
    float (*Ps)[68] = (float(*)[68])(sm + 3 * 64 * 68);// [k][q] / [d][q]

    const int qt = blockIdx.x;
    const int bh = blockIdx.y;
    const int s  = blockIdx.z;
    const int b2 = bh >> 2, h = bh & 3;
    const int q0 = qt << 6;
    const int tid = threadIdx.x;
    const int tx = tid & 15, ty = tid >> 4;

    size_t base = (size_t)s * TEN + (size_t)b2 * (DD * NN);
    const float* __restrict__ qp = g_q + base;
    const float* __restrict__ kp = g_k + base;
    const float* __restrict__ vp = g_v + base;
    float* mp = g_msg + base;

    for (int e = tid; e < 4096; e += 256) {
        int qi = e & 63, d = e >> 6;
        Qs[d][qi] = qp[(size_t)(d * 4 + h) * NN + q0 + qi] * 0.125f;
    }

    float o[4][4] = {};
    float mi[4], li[4];
    #pragma unroll
    for (int i = 0; i < 4; i++) { mi[i] = -1e30f; li[i] = 0.f; }

    for (int kt = 0; kt < 16; kt++) {
        int m0k = kt << 6;
        __syncthreads();   // previous PV done reading Vs/Ps
        for (int e = tid; e < 4096; e += 256) {
            int kk = e & 63, d = e >> 6;
            float kv = kp[(size_t)(d * 4 + h) * NN + m0k + kk];
            float vv = vp[(size_t)(d * 4 + h) * NN + m0k + kk];
            Ks[d][kk] = kv;
            Vs[kk][d] = vv;
        }
        __syncthreads();

        float sreg[4][4] = {};
        #pragma unroll 8
        for (int d = 0; d < 64; d++) {
            float4 qv = *(const float4*)&Qs[d][ty * 4];
            float4 kv = *(const float4*)&Ks[d][tx * 4];
            float qa[4] = {qv.x, qv.y, qv.z, qv.w};
            float ka[4] = {kv.x, kv.y, kv.z, kv.w};
            #pragma unroll
            for (int i = 0; i < 4; i++)
                #pragma unroll
                for (int j = 0; j < 4; j++)
                    sreg[i][j] = fmaf(qa[i], ka[j], sreg[i][j]);
        }

        // online softmax per query row; rows replicated across the 16 tx lanes
        #pragma unroll
        for (int i = 0; i < 4; i++) {
            float rm = fmaxf(fmaxf(sreg[i][0], sreg[i][1]),
                             fmaxf(sreg[i][2], sreg[i][3]));
            rm = fmaxf(rm, __shfl_xor_sync(0xffffffffu, rm, 1));
            rm = fmaxf(rm, __shfl_xor_sync(0xffffffffu, rm, 2));
            rm = fmaxf(rm, __shfl_xor_sync(0xffffffffu, rm, 4));
            rm = fmaxf(rm, __shfl_xor_sync(0xffffffffu, rm, 8));
            float mn = fmaxf(mi[i], rm);
            float alpha = __expf(mi[i] - mn);
            mi[i] = mn;
            float rs = 0.f;
            #pragma unroll
            for (int j = 0; j < 4; j++) {
                float p = __expf(sreg[i][j] - mn);
                sreg[i][j] = p;
                rs += p;
            }
            rs += __shfl_xor_sync(0xffffffffu, rs, 1);
            rs += __shfl_xor_sync(0xffffffffu, rs, 2);
            rs += __shfl_xor_sync(0xffffffffu, rs, 4);
            rs += __shfl_xor_sync(0xffffffffu, rs, 8);
            li[i] = li[i] * alpha + rs;
            #pragma unroll
            for (int j = 0; j < 4; j++) o[i][j] *= alpha;
        }

        #pragma unroll
        for (int i = 0; i < 4; i++)
            #pragma unroll
            for (int j = 0; j < 4; j++)
                Ps[tx * 4 + j][ty * 4 + i] = sreg[i][j];
        __syncthreads();

        #pragma unroll 8
        for (int kk = 0; kk < 64; kk++) {
            float4 pv = *(const float4*)&Ps[kk][ty * 4];
            float4 vv = *(const float4*)&Vs[kk][tx * 4];
            float pa[4] = {pv.x, pv.y, pv.z, pv.w};
            float va[4] = {vv.x, vv.y, vv.z, vv.w};
            #pragma unroll
            for (int i = 0; i < 4; i++)
                #pragma unroll
                for (int j = 0; j < 4; j++)
                    o[i][j] = fmaf(pa[i], va[j], o[i][j]);
        }
    }

    float inv[4];
    #pragma unroll
    for (int i = 0; i < 4; i++) inv[i] = 1.f / li[i];
    __syncthreads();
    #pragma unroll
    for (int i = 0; i < 4; i++)
        #pragma unroll
        for (int j = 0; j < 4; j++)
            Ps[tx * 4 + j][ty * 4 + i] = o[i][j] * inv[i];
    __syncthreads();
    for (int e = tid; e < 4096; e += 256) {
        int qi = e & 63, d = e >> 6;
        mp[(size_t)(d * 4 + h) * NN + q0 + qi] = Ps[d][qi];
    }
}

// ---------------------------------------------------------------------------
// BatchNorm stats on g_h: per (stream, channel) biased mean/var over 2048
// elements -> fused scale/shift in g_stats. grid = (512, 2), block = 256.
// ---------------------------------------------------------------------------
__global__ __launch_bounds__(256) void bn_stats_kernel(const float* __restrict__ g1,
                                                       const float* __restrict__ be1) {
    const int c = blockIdx.x;
    const int s = blockIdx.y;
    const float* hp = g_h + (size_t)s * HTEN;
    int tid = threadIdx.x;
    float sum = 0.f, sq = 0.f;
    for (int idx = tid; idx < 2048; idx += 256) {
        int b2 = idx >> 10, n = idx & 1023;
        float v = hp[((size_t)b2 * 512 + c) * NN + n];
        sum += v;
        sq = fmaf(v, v, sq);
    }
    #pragma unroll
    for (int w = 16; w; w >>= 1) {
        sum += __shfl_xor_sync(0xffffffffu, sum, w);
        sq  += __shfl_xor_sync(0xffffffffu, sq,  w);
    }
    __shared__ float ssum[8], ssq[8];
    int wid = tid >> 5, lane = tid & 31;
    if (lane == 0) { ssum[wid] = sum; ssq[wid] = sq; }
    __syncthreads();
    if (tid == 0) {
        float S = 0.f, Q = 0.f;
        #pragma unroll
        for (int i = 0; i < 8; i++) { S += ssum[i]; Q += ssq[i]; }
        float mean = S * (1.f / 2048.f);
        float var  = Q * (1.f / 2048.f) - mean * mean;
        float rstd = rsqrtf(var + 1e-5f);
        float sc = rstd * g1[c];
        float sh = be1[c] - mean * sc;
        g_stats[(s * 512 + c) * 2 + 0] = sc;
        g_stats[(s * 512 + c) * 2 + 1] = sh;
    }
}

// ---------------------------------------------------------------------------
// Host orchestration
// ---------------------------------------------------------------------------
extern "C" void kernel_launch(void* const* d_in, const int* in_sizes, int n_in,
                              void* d_out, int out_size) {
    const float* desc0 = (const float*)d_in[0];
    const float* desc1 = (const float*)d_in[1];
    const float* Wq  = (const float*)d_in[2];
    const float* bq  = (const float*)d_in[3];
    const float* Wk  = (const float*)d_in[4];
    const float* bk  = (const float*)d_in[5];
    const float* Wv  = (const float*)d_in[6];
    const float* bv  = (const float*)d_in[7];
    const float* Wm  = (const float*)d_in[8];
    const float* bm  = (const float*)d_in[9];
    const float* W1  = (const float*)d_in[10];
    const float* b1  = (const float*)d_in[11];
    const float* g1  = (const float*)d_in[12];
    const float* be1 = (const float*)d_in[13];
    const float* W2  = (const float*)d_in[14];
    const float* b2  = (const float*)d_in[15];
    float* out = (float*)d_out;

    float *qb, *kb, *vb, *msgb, *mmb, *hb, *statsb;
    cudaGetSymbolAddress((void**)&qb,    g_q);
    cudaGetSymbolAddress((void**)&kb,    g_k);
    cudaGetSymbolAddress((void**)&vb,    g_v);
    cudaGetSymbolAddress((void**)&msgb,  g_msg);
    cudaGetSymbolAddress((void**)&mmb,   g_mm);
    cudaGetSymbolAddress((void**)&hb,    g_h);
    cudaGetSymbolAddress((void**)&statsb, g_stats);

    cudaFuncSetAttribute(attn_kernel,
                         cudaFuncAttributeMaxDynamicSharedMemorySize, ATTN_SMEM);

    // outs[2] = desc0, outs[3] = desc1 (faithful quirk)
    cudaMemcpyAsync(out + 2 * (size_t)TEN, desc0, TEN * sizeof(float),
                    cudaMemcpyDeviceToDevice, 0);
    cudaMemcpyAsync(out + 3 * (size_t)TEN, desc1, TEN * sizeof(float),
                    cudaMemcpyDeviceToDevice, 0);

    auto launch_gemm = [&](const float* W, const float* bias,
                           const float* x0a, const float* x0b,
                           const float* x1a, const float* x1b,
                           const float* resa, const float* resb,
                           int use_bn, float* outa, float* outb,
                           int M, int K, int K0) {
        GemmArgs ga;
        ga.W = W; ga.bias = bias;
        ga.X0[0] = x0a; ga.X0[1] = x0b;
        ga.X1[0] = x1a; ga.X1[1] = x1b;
        ga.res[0] = resa; ga.res[1] = resb;
        ga.bnp[0] = statsb; ga.bnp[1] = statsb + 1024;
        ga.out[0] = outa; ga.out[1] = outb;
        ga.M = M; ga.K = K; ga.K0 = K0; ga.use_bn = use_bn;
        dim3 grid(32, M / 64, 2);
        gemm_kernel<<<grid, 256>>>(ga);
    };

    const float* xa = desc0;
    const float* xb = desc1;

    for (int i = 0; i < 18; i++) {
        const float *sa, *sb, *ra, *rb;
        float *oa, *ob;
        if (i == 0) {
            sa = xa; sb = xb; ra = desc0; rb = desc1;
            oa = out;            ob = out + (size_t)TEN;
        } else if (i == 1) {
            sa = xb; sb = xa; ra = desc0; rb = desc1;          // cross, residual to originals
            oa = out + 4 * (size_t)TEN; ob = out + 5 * (size_t)TEN;
        } else {
            if ((i & 1) == 0) { sa = xa; sb = xb; }            // self
            else              { sa = xb; sb = xa; }            // cross
            ra = xa; rb = xb;
            oa = out + (size_t)(2 + 2 * i) * TEN;
            ob = oa + (size_t)TEN;
        }

        const float* Wq_i = Wq + (size_t)i * DD * DD;
        const float* Wk_i = Wk + (size_t)i * DD * DD;
        const float* Wv_i = Wv + (size_t)i * DD * DD;
        const float* Wm_i = Wm + (size_t)i * DD * DD;
        const float* W1_i = W1 + (size_t)i * 512 * 512;
        const float* W2_i = W2 + (size_t)i * 256 * 512;
        const float* bq_i = bq + (size_t)i * DD;
        const float* bk_i = bk + (size_t)i * DD;
        const float* bv_i = bv + (size_t)i * DD;
        const float* bm_i = bm + (size_t)i * DD;
        const float* b1_i = b1 + (size_t)i * 512;
        const float* b2_i = b2 + (size_t)i * 256;
        const float* g1_i = g1 + (size_t)i * 512;
        const float* be_i = be1 + (size_t)i * 512;

        // q = Wq x + bq   (from x);  k,v from src
        launch_gemm(Wq_i, bq_i, xa, xb, nullptr, nullptr, nullptr, nullptr, 0,
                    qb, qb + TEN, 256, 256, 256);
        launch_gemm(Wk_i, bk_i, sa, sb, nullptr, nullptr, nullptr, nullptr, 0,
                    kb, kb + TEN, 256, 256, 256);
        launch_gemm(Wv_i, bv_i, sa, sb, nullptr, nullptr, nullptr, nullptr, 0,
                    vb, vb + TEN, 256, 256, 256);

        // attention -> g_msg
        attn_kernel<<<dim3(16, 8, 2), 256, ATTN_SMEM>>>();

        // msg projection
        launch_gemm(Wm_i, bm_i, msgb, msgb + TEN, nullptr, nullptr,
                    nullptr, nullptr, 0, mmb, mmb + TEN, 256, 256, 256);

        // h = W1 [x; msg] + b1
        launch_gemm(W1_i, b1_i, xa, xb, mmb, mmb + TEN,
                    nullptr, nullptr, 0, hb, hb + HTEN, 512, 512, 256);

        // BN stats -> scale/shift
        bn_stats_kernel<<<dim3(512, 2), 256>>>(g1_i, be_i);

        // out = res + W2 relu(BN(h)) + b2
        launch_gemm(W2_i, b2_i, hb, hb + HTEN, nullptr, nullptr,
                    ra, rb, 1, oa, ob, 256, 512, 512);

        xa = oa; xb = ob;
    }
}

// round 3
// speedup vs baseline: 1.3702x; 1.3702x over previous
#include <cuda_runtime.h>
#include <math.h>

// ---------------------------------------------------------------------------
// AttentionalGNN: L=18 layers, D=256, H=4 (head dim 64), B=2, N=1024.
// Layout of all activations: [b2][C][N] (row n contiguous), fp32.
// Channel->head mapping (from reshape(b, HD, H, -1)): c = d*4 + h.
// Round 3: GEMMs on tensor cores via 3xTF32 error-compensated mma.sync
// (hi/lo split of both operands; drops only the lo*lo term ~2^-22).
// ---------------------------------------------------------------------------

#define BB   2
#define DD   256
#define NN   1024
#define HH   4
#define HDIM 64
#define TEN  (BB*DD*NN)      // 524288 elems = one [2,256,1024] tensor
#define HTEN (BB*512*NN)     // 1048576 elems = one [2,512,1024] tensor

// Scratch (device globals; no allocation anywhere). [stream][b2][C][N]
__device__ float g_q  [2*TEN];
__device__ float g_k  [2*TEN];
__device__ float g_v  [2*TEN];
__device__ float g_msg[2*TEN];
__device__ float g_mm [2*TEN];
__device__ float g_h  [2*HTEN];
__device__ float g_stats[2*512*2];   // per stream, per channel: scale, shift

// ---------------------------------------------------------------------------
// tf32 helpers
// ---------------------------------------------------------------------------
__device__ __forceinline__ float to_tf32(float x) {
    unsigned u;
    asm("cvt.rna.tf32.f32 %0, %1;" : "=r"(u) : "f"(x));
    return __uint_as_float(u);
}

#define MMA_TF32(acc, af, bf)                                                  \
    asm volatile(                                                              \
        "mma.sync.aligned.m16n8k8.row.col.f32.tf32.tf32.f32 "                  \
        "{%0,%1,%2,%3}, {%4,%5,%6,%7}, {%8,%9}, {%0,%1,%2,%3};"                \
        : "+f"(acc[0]), "+f"(acc[1]), "+f"(acc[2]), "+f"(acc[3])               \
        : "r"(af[0]), "r"(af[1]), "r"(af[2]), "r"(af[3]),                      \
          "r"(bf[0]), "r"(bf[1]))

// ---------------------------------------------------------------------------
// Tensor-core GEMM (3xTF32): out = W @ X + bias, with fusions:
// concat-K (two X sources), BN(normalize)+relu on X load, residual epilogue.
// Block tile: 128(M) x 64(N) x 32(K). 8 warps (4 M x 2 N), warp tile 32x32.
// grid = (32 [b2*16 + ntile], M/128, 2 streams), block = 256.
// Dynamic smem: As_hi/As_lo [128][36], Bs_hi/Bs_lo [32][68]  = 54272 B.
// ---------------------------------------------------------------------------
struct GemmArgs {
    const float* W;
    const float* bias;
    const float* X0[2];
    const float* X1[2];
    const float* res[2];
    const float* bnp[2];
    float*       out[2];
    int M, K, K0, use_bn;
};

#define BM 128
#define BN 64
#define BK 32
#define ASTRIDE 36
#define BSTRIDE 68
#define GEMM_SMEM ((2*BM*ASTRIDE + 2*BK*BSTRIDE) * 4)

__global__ __launch_bounds__(256) void gemm_tc(GemmArgs a) {
    extern __shared__ __align__(16) float smem[];
    float (*As_hi)[ASTRIDE] = (float(*)[ASTRIDE])(smem);
    float (*As_lo)[ASTRIDE] = (float(*)[ASTRIDE])(smem + BM * ASTRIDE);
    float (*Bs_hi)[BSTRIDE] = (float(*)[BSTRIDE])(smem + 2 * BM * ASTRIDE);
    float (*Bs_lo)[BSTRIDE] = (float(*)[BSTRIDE])(smem + 2 * BM * ASTRIDE + BK * BSTRIDE);

    const int s  = blockIdx.z;
    const int jt = blockIdx.x;
    const int b2 = jt >> 4;
    const int n0 = (jt & 15) * BN;
    const int m0 = blockIdx.y * BM;
    const int tid  = threadIdx.x;
    const int warp = tid >> 5, lane = tid & 31;
    const int wm0 = (warp >> 1) * 32;     // warp M offset (4 warps)
    const int wn0 = (warp & 1) * 32;      // warp N offset (2 warps)
    const int g = lane >> 2, t = lane & 3;

    const int K = a.K, K0 = a.K0, M = a.M;
    const float* __restrict__ W   = a.W;
    const float* __restrict__ X0  = a.X0[s];
    const float* __restrict__ X1  = a.X1[s];
    const float* __restrict__ bnp = a.bnp[s];

    float acc[2][4][4];
    #pragma unroll
    for (int mi = 0; mi < 2; mi++)
        #pragma unroll
        for (int ni = 0; ni < 4; ni++)
            #pragma unroll
            for (int r = 0; r < 4; r++) acc[mi][ni][r] = 0.f;

    for (int k0 = 0; k0 < K; k0 += BK) {
        // stage A: W[m0..m0+127][k0..k0+31], hi/lo split
        #pragma unroll
        for (int e = tid; e < BM * BK / 4; e += 256) {
            int m  = e >> 3;
            int kq = (e & 7) * 4;
            float4 w = *(const float4*)&W[(size_t)(m0 + m) * K + k0 + kq];
            float wa[4] = {w.x, w.y, w.z, w.w};
            #pragma unroll
            for (int q = 0; q < 4; q++) {
                float hi = to_tf32(wa[q]);
                As_hi[m][kq + q] = hi;
                As_lo[m][kq + q] = to_tf32(wa[q] - hi);
            }
        }
        // stage B: X[k0..k0+31][n0..n0+63] with concat + BN/relu fusion
        #pragma unroll
        for (int e = tid; e < BK * BN / 4; e += 256) {
            int kk = e >> 4;
            int nq = (e & 15) * 4;
            int k = k0 + kk;
            float4 v;
            if (k < K0) v = *(const float4*)&X0[((size_t)b2 * K0 + k) * NN + n0 + nq];
            else        v = *(const float4*)&X1[((size_t)b2 * (K - K0) + (k - K0)) * NN + n0 + nq];
            float va[4] = {v.x, v.y, v.z, v.w};
            if (a.use_bn) {
                float sc = bnp[2 * k], sh = bnp[2 * k + 1];
                #pragma unroll
                for (int q = 0; q < 4; q++)
                    va[q] = fmaxf(fmaf(va[q], sc, sh), 0.f);
            }
            #pragma unroll
            for (int q = 0; q < 4; q++) {
                float hi = to_tf32(va[q]);
                Bs_hi[kk][nq + q] = hi;
                Bs_lo[kk][nq + q] = to_tf32(va[q] - hi);
            }
        }
        __syncthreads();

        #pragma unroll
        for (int kk = 0; kk < BK; kk += 8) {
            unsigned afh[2][4], afl[2][4];
            #pragma unroll
            for (int mi = 0; mi < 2; mi++) {
                int r0 = wm0 + mi * 16 + g;
                afh[mi][0] = __float_as_uint(As_hi[r0    ][kk + t    ]);
                afh[mi][1] = __float_as_uint(As_hi[r0 + 8][kk + t    ]);
                afh[mi][2] = __float_as_uint(As_hi[r0    ][kk + t + 4]);
                afh[mi][3] = __float_as_uint(As_hi[r0 + 8][kk + t + 4]);
                afl[mi][0] = __float_as_uint(As_lo[r0    ][kk + t    ]);
                afl[mi][1] = __float_as_uint(As_lo[r0 + 8][kk + t    ]);
                afl[mi][2] = __float_as_uint(As_lo[r0    ][kk + t + 4]);
                afl[mi][3] = __float_as_uint(As_lo[r0 + 8][kk + t + 4]);
            }
            unsigned bfh[4][2], bfl[4][2];
            #pragma unroll
            for (int ni = 0; ni < 4; ni++) {
                int c = wn0 + ni * 8 + g;
                bfh[ni][0] = __float_as_uint(Bs_hi[kk + t    ][c]);
                bfh[ni][1] = __float_as_uint(Bs_hi[kk + t + 4][c]);
                bfl[ni][0] = __float_as_uint(Bs_lo[kk + t    ][c]);
                bfl[ni][1] = __float_as_uint(Bs_lo[kk + t + 4][c]);
            }
            // cross terms first, then hi*hi
            #pragma unroll
            for (int mi = 0; mi < 2; mi++)
                #pragma unroll
                for (int ni = 0; ni < 4; ni++) {
                    MMA_TF32(acc[mi][ni], afh[mi], bfl[ni]);
                    MMA_TF32(acc[mi][ni], afl[mi], bfh[ni]);
                    MMA_TF32(acc[mi][ni], afh[mi], bfh[ni]);
                }
        }
        __syncthreads();
    }

    // epilogue: bias + optional residual, float2 stores
    const float* resp = a.res[s];
    float* outp = a.out[s];
    #pragma unroll
    for (int mi = 0; mi < 2; mi++) {
        #pragma unroll
        for (int half = 0; half < 2; half++) {
            int mrel = wm0 + mi * 16 + g + half * 8;
            int m = m0 + mrel;
            float bb = a.bias[m];
            #pragma unroll
            for (int ni = 0; ni < 4; ni++) {
                int col = n0 + wn0 + ni * 8 + 2 * t;
                size_t off = ((size_t)b2 * M + m) * NN + col;
                float2 c;
                c.x = acc[mi][ni][2 * half + 0] + bb;
                c.y = acc[mi][ni][2 * half + 1] + bb;
                if (resp) {
                    float2 r = *(const float2*)(resp + off);
                    c.x += r.x; c.y += r.y;
                }
                *(float2*)(outp + off) = c;
            }
        }
    }
}

// ---------------------------------------------------------------------------
// Flash-style attention on scratch buffers g_q/g_k/g_v -> g_msg.
// grid = (16 qtiles, 8 = b2*4+h, 2 streams), block = 256, dyn smem 69632B.
// Channel of (d,h) is d*4+h. SCALE folded into Q load.
// ---------------------------------------------------------------------------
#define ATTN_SMEM (4 * 64 * 68 * 4)

__global__ __launch_bounds__(256) void attn_kernel() {
    extern __shared__ __align__(16) float sm[];
    float (*Qs)[68] = (float(*)[68])(sm);              // [d][q]
    float (*Ks)[68] = (float(*)[68])(sm + 64 * 68);    // [d][k]
    float (*Vs)[68] = (float(*)[68])(sm + 2 * 64 * 68);// [k][d]
    float (*Ps)[68] = (float(*)[68])(sm + 3 * 64 * 68);// [k][q] / [d][q]

    const int qt = blockIdx.x;
    const int bh = blockIdx.y;
    const int s  = blockIdx.z;
    const int b2 = bh >> 2, h = bh & 3;
    const int q0 = qt << 6;
    const int tid = threadIdx.x;
    const int tx = tid & 15, ty = tid >> 4;

    size_t base = (size_t)s * TEN + (size_t)b2 * (DD * NN);
    const float* __restrict__ qp = g_q + base;
    const float* __restrict__ kp = g_k + base;
    const float* __restrict__ vp = g_v + base;
    float* mp = g_msg + base;

    for (int e = tid; e < 4096; e += 256) {
        int qi = e & 63, d = e >> 6;
        Qs[d][qi] = qp[(size_t)(d * 4 + h) * NN + q0 + qi] * 0.125f;
    }

    float o[4][4] = {};
    float mi[4], li[4];
    #pragma unroll
    for (int i = 0; i < 4; i++) { mi[i] = -1e30f; li[i] = 0.f; }

    for (int kt = 0; kt < 16; kt++) {
        int m0k = kt << 6;
        __syncthreads();   // previous PV done reading Vs/Ps
        for (int e = tid; e < 4096; e += 256) {
            int kk = e & 63, d = e >> 6;
            float kv = kp[(size_t)(d * 4 + h) * NN + m0k + kk];
            float vv = vp[(size_t)(d * 4 + h) * NN + m0k + kk];
            Ks[d][kk] = kv;
            Vs[kk][d] = vv;
        }
        __syncthreads();

        float sreg[4][4] = {};
        #pragma unroll 8
        for (int d = 0; d < 64; d++) {
            float4 qv = *(const float4*)&Qs[d][ty * 4];
            float4 kv = *(const float4*)&Ks[d][tx * 4];
            float qa[4] = {qv.x, qv.y, qv.z, qv.w};
            float ka[4] = {kv.x, kv.y, kv.z, kv.w};
            #pragma unroll
            for (int i = 0; i < 4; i++)
                #pragma unroll
                for (int j = 0; j < 4; j++)
                    sreg[i][j] = fmaf(qa[i], ka[j], sreg[i][j]);
        }

        // online softmax per query row; rows replicated across the 16 tx lanes
        #pragma unroll
        for (int i = 0; i < 4; i++) {
            float rm = fmaxf(fmaxf(sreg[i][0], sreg[i][1]),
                             fmaxf(sreg[i][2], sreg[i][3]));
            rm = fmaxf(rm, __shfl_xor_sync(0xffffffffu, rm, 1));
            rm = fmaxf(rm, __shfl_xor_sync(0xffffffffu, rm, 2));
            rm = fmaxf(rm, __shfl_xor_sync(0xffffffffu, rm, 4));
            rm = fmaxf(rm, __shfl_xor_sync(0xffffffffu, rm, 8));
            float mn = fmaxf(mi[i], rm);
            float alpha = __expf(mi[i] - mn);
            mi[i] = mn;
            float rs = 0.f;
            #pragma unroll
            for (int j = 0; j < 4; j++) {
                float p = __expf(sreg[i][j] - mn);
                sreg[i][j] = p;
                rs += p;
            }
            rs += __shfl_xor_sync(0xffffffffu, rs, 1);
            rs += __shfl_xor_sync(0xffffffffu, rs, 2);
            rs += __shfl_xor_sync(0xffffffffu, rs, 4);
            rs += __shfl_xor_sync(0xffffffffu, rs, 8);
            li[i] = li[i] * alpha + rs;
            #pragma unroll
            for (int j = 0; j < 4; j++) o[i][j] *= alpha;
        }

        #pragma unroll
        for (int i = 0; i < 4; i++)
            #pragma unroll
            for (int j = 0; j < 4; j++)
                Ps[tx * 4 + j][ty * 4 + i] = sreg[i][j];
        __syncthreads();

        #pragma unroll 8
        for (int kk = 0; kk < 64; kk++) {
            float4 pv = *(const float4*)&Ps[kk][ty * 4];
            float4 vv = *(const float4*)&Vs[kk][tx * 4];
            float pa[4] = {pv.x, pv.y, pv.z, pv.w};
            float va[4] = {vv.x, vv.y, vv.z, vv.w};
            #pragma unroll
            for (int i = 0; i < 4; i++)
                #pragma unroll
                for (int j = 0; j < 4; j++)
                    o[i][j] = fmaf(pa[i], va[j], o[i][j]);
        }
    }

    float inv[4];
    #pragma unroll
    for (int i = 0; i < 4; i++) inv[i] = 1.f / li[i];
    __syncthreads();
    #pragma unroll
    for (int i = 0; i < 4; i++)
        #pragma unroll
        for (int j = 0; j < 4; j++)
            Ps[tx * 4 + j][ty * 4 + i] = o[i][j] * inv[i];
    __syncthreads();
    for (int e = tid; e < 4096; e += 256) {
        int qi = e & 63, d = e >> 6;
        mp[(size_t)(d * 4 + h) * NN + q0 + qi] = Ps[d][qi];
    }
}

// ---------------------------------------------------------------------------
// BatchNorm stats on g_h: per (stream, channel) biased mean/var over 2048
// elements -> fused scale/shift in g_stats. grid = (512, 2), block = 256.
// ---------------------------------------------------------------------------
__global__ __launch_bounds__(256) void bn_stats_kernel(const float* __restrict__ g1,
                                                       const float* __restrict__ be1) {
    const int c = blockIdx.x;
    const int s = blockIdx.y;
    const float* hp = g_h + (size_t)s * HTEN;
    int tid = threadIdx.x;
    float sum = 0.f, sq = 0.f;
    for (int idx = tid; idx < 2048; idx += 256) {
        int b2 = idx >> 10, n = idx & 1023;
        float v = hp[((size_t)b2 * 512 + c) * NN + n];
        sum += v;
        sq = fmaf(v, v, sq);
    }
    #pragma unroll
    for (int w = 16; w; w >>= 1) {
        sum += __shfl_xor_sync(0xffffffffu, sum, w);
        sq  += __shfl_xor_sync(0xffffffffu, sq,  w);
    }
    __shared__ float ssum[8], ssq[8];
    int wid = tid >> 5, lane = tid & 31;
    if (lane == 0) { ssum[wid] = sum; ssq[wid] = sq; }
    __syncthreads();
    if (tid == 0) {
        float S = 0.f, Q = 0.f;
        #pragma unroll
        for (int i = 0; i < 8; i++) { S += ssum[i]; Q += ssq[i]; }
        float mean = S * (1.f / 2048.f);
        float var  = Q * (1.f / 2048.f) - mean * mean;
        float rstd = rsqrtf(var + 1e-5f);
        float sc = rstd * g1[c];
        float sh = be1[c] - mean * sc;
        g_stats[(s * 512 + c) * 2 + 0] = sc;
        g_stats[(s * 512 + c) * 2 + 1] = sh;
    }
}

// ---------------------------------------------------------------------------
// Host orchestration
// ---------------------------------------------------------------------------
extern "C" void kernel_launch(void* const* d_in, const int* in_sizes, int n_in,
                              void* d_out, int out_size) {
    const float* desc0 = (const float*)d_in[0];
    const float* desc1 = (const float*)d_in[1];
    const float* Wq  = (const float*)d_in[2];
    const float* bq  = (const float*)d_in[3];
    const float* Wk  = (const float*)d_in[4];
    const float* bk  = (const float*)d_in[5];
    const float* Wv  = (const float*)d_in[6];
    const float* bv  = (const float*)d_in[7];
    const float* Wm  = (const float*)d_in[8];
    const float* bm  = (const float*)d_in[9];
    const float* W1  = (const float*)d_in[10];
    const float* b1  = (const float*)d_in[11];
    const float* g1  = (const float*)d_in[12];
    const float* be1 = (const float*)d_in[13];
    const float* W2  = (const float*)d_in[14];
    const float* b2  = (const float*)d_in[15];
    float* out = (float*)d_out;

    float *qb, *kb, *vb, *msgb, *mmb, *hb, *statsb;
    cudaGetSymbolAddress((void**)&qb,    g_q);
    cudaGetSymbolAddress((void**)&kb,    g_k);
    cudaGetSymbolAddress((void**)&vb,    g_v);
    cudaGetSymbolAddress((void**)&msgb,  g_msg);
    cudaGetSymbolAddress((void**)&mmb,   g_mm);
    cudaGetSymbolAddress((void**)&hb,    g_h);
    cudaGetSymbolAddress((void**)&statsb, g_stats);

    cudaFuncSetAttribute(attn_kernel,
                         cudaFuncAttributeMaxDynamicSharedMemorySize, ATTN_SMEM);
    cudaFuncSetAttribute(gemm_tc,
                         cudaFuncAttributeMaxDynamicSharedMemorySize, GEMM_SMEM);

    // outs[2] = desc0, outs[3] = desc1 (faithful quirk)
    cudaMemcpyAsync(out + 2 * (size_t)TEN, desc0, TEN * sizeof(float),
                    cudaMemcpyDeviceToDevice, 0);
    cudaMemcpyAsync(out + 3 * (size_t)TEN, desc1, TEN * sizeof(float),
                    cudaMemcpyDeviceToDevice, 0);

    auto launch_gemm = [&](const float* W, const float* bias,
                           const float* x0a, const float* x0b,
                           const float* x1a, const float* x1b,
                           const float* resa, const float* resb,
                           int use_bn, float* outa, float* outb,
                           int M, int K, int K0) {
        GemmArgs ga;
        ga.W = W; ga.bias = bias;
        ga.X0[0] = x0a; ga.X0[1] = x0b;
        ga.X1[0] = x1a; ga.X1[1] = x1b;
        ga.res[0] = resa; ga.res[1] = resb;
        ga.bnp[0] = statsb; ga.bnp[1] = statsb + 1024;
        ga.out[0] = outa; ga.out[1] = outb;
        ga.M = M; ga.K = K; ga.K0 = K0; ga.use_bn = use_bn;
        dim3 grid(32, M / BM, 2);
        gemm_tc<<<grid, 256, GEMM_SMEM>>>(ga);
    };

    const float* xa = desc0;
    const float* xb = desc1;

    for (int i = 0; i < 18; i++) {
        const float *sa, *sb, *ra, *rb;
        float *oa, *ob;
        if (i == 0) {
            sa = xa; sb = xb; ra = desc0; rb = desc1;
            oa = out;            ob = out + (size_t)TEN;
        } else if (i == 1) {
            sa = xb; sb = xa; ra = desc0; rb = desc1;          // cross, residual to originals
            oa = out + 4 * (size_t)TEN; ob = out + 5 * (size_t)TEN;
        } else {
            if ((i & 1) == 0) { sa = xa; sb = xb; }            // self
            else              { sa = xb; sb = xa; }            // cross
            ra = xa; rb = xb;
            oa = out + (size_t)(2 + 2 * i) * TEN;
            ob = oa + (size_t)TEN;
        }

        const float* Wq_i = Wq + (size_t)i * DD * DD;
        const float* Wk_i = Wk + (size_t)i * DD * DD;
        const float* Wv_i = Wv + (size_t)i * DD * DD;
        const float* Wm_i = Wm + (size_t)i * DD * DD;
        const float* W1_i = W1 + (size_t)i * 512 * 512;
        const float* W2_i = W2 + (size_t)i * 256 * 512;
        const float* bq_i = bq + (size_t)i * DD;
        const float* bk_i = bk + (size_t)i * DD;
        const float* bv_i = bv + (size_t)i * DD;
        const float* bm_i = bm + (size_t)i * DD;
        const float* b1_i = b1 + (size_t)i * 512;
        const float* b2_i = b2 + (size_t)i * 256;
        const float* g1_i = g1 + (size_t)i * 512;
        const float* be_i = be1 + (size_t)i * 512;

        // q = Wq x + bq   (from x);  k,v from src
        launch_gemm(Wq_i, bq_i, xa, xb, nullptr, nullptr, nullptr, nullptr, 0,
                    qb, qb + TEN, 256, 256, 256);
        launch_gemm(Wk_i, bk_i, sa, sb, nullptr, nullptr, nullptr, nullptr, 0,
                    kb, kb + TEN, 256, 256, 256);
        launch_gemm(Wv_i, bv_i, sa, sb, nullptr, nullptr, nullptr, nullptr, 0,
                    vb, vb + TEN, 256, 256, 256);

        // attention -> g_msg
        attn_kernel<<<dim3(16, 8, 2), 256, ATTN_SMEM>>>();

        // msg projection
        launch_gemm(Wm_i, bm_i, msgb, msgb + TEN, nullptr, nullptr,
                    nullptr, nullptr, 0, mmb, mmb + TEN, 256, 256, 256);

        // h = W1 [x; msg] + b1
        launch_gemm(W1_i, b1_i, xa, xb, mmb, mmb + TEN,
                    nullptr, nullptr, 0, hb, hb + HTEN, 512, 512, 256);

        // BN stats -> scale/shift
        bn_stats_kernel<<<dim3(512, 2), 256>>>(g1_i, be_i);

        // out = res + W2 relu(BN(h)) + b2
        launch_gemm(W2_i, b2_i, hb, hb + HTEN, nullptr, nullptr,
                    ra, rb, 1, oa, ob, 256, 512, 512);

        xa = oa; xb = ob;
    }
}

// round 4
// speedup vs baseline: 1.3924x; 1.0162x over previous
#include <cuda_runtime.h>
#include <math.h>

// ---------------------------------------------------------------------------
// AttentionalGNN: L=18 layers, D=256, H=4 (head dim 64), B=2, N=1024.
// Activations: [b2][C][N] fp32, channel c = d*4 + h.
// Round 4: weights pre-split to tf32 hi/lo once per launch; GEMM retiled
// (BM=64/BN=64, 128 thr), qkv merged into one launch. 3xTF32 numerics.
// ---------------------------------------------------------------------------

#define BB   2
#define DD   256
#define NN   1024
#define TEN  (BB*DD*NN)
#define HTEN (BB*512*NN)

// Scratch (device globals). [stream][b2][C][N]
__device__ float g_q  [2*TEN];
__device__ float g_k  [2*TEN];
__device__ float g_v  [2*TEN];
__device__ float g_msg[2*TEN];
__device__ float g_mm [2*TEN];
__device__ float g_h  [2*HTEN];
__device__ float g_stats[2*512*2];

// Pre-split weights (hi/lo), concatenated: Wq|Wk|Wv|Wm|W1|W2
#define SZ_D  (18L*256*256)          // 1179648
#define SZ_1  (18L*512*512)          // 4718592
#define SZ_2  (18L*256*512)          // 2359296
#define OFF_WQ 0L
#define OFF_WK (SZ_D)
#define OFF_WV (2*SZ_D)
#define OFF_WM (3*SZ_D)
#define OFF_W1 (4*SZ_D)
#define OFF_W2 (4*SZ_D + SZ_1)
#define TOTW   (4*SZ_D + SZ_1 + SZ_2) // 11796480
__device__ float g_whi[TOTW];
__device__ float g_wlo[TOTW];

__device__ __forceinline__ float to_tf32(float x) {
    unsigned u;
    asm("cvt.rna.tf32.f32 %0, %1;" : "=r"(u) : "f"(x));
    return __uint_as_float(u);
}

#define MMA_TF32(acc, af, bf)                                                  \
    asm volatile(                                                              \
        "mma.sync.aligned.m16n8k8.row.col.f32.tf32.tf32.f32 "                  \
        "{%0,%1,%2,%3}, {%4,%5,%6,%7}, {%8,%9}, {%0,%1,%2,%3};"                \
        : "+f"(acc[0]), "+f"(acc[1]), "+f"(acc[2]), "+f"(acc[3])               \
        : "r"(af[0]), "r"(af[1]), "r"(af[2]), "r"(af[3]),                      \
          "r"(bf[0]), "r"(bf[1]))

// ---------------------------------------------------------------------------
// Weight pre-split: w -> hi = tf32(w), lo = w - hi (raw; hw truncates on use)
// ---------------------------------------------------------------------------
__global__ __launch_bounds__(256) void presplit_kernel(
    const float* __restrict__ Wq, const float* __restrict__ Wk,
    const float* __restrict__ Wv, const float* __restrict__ Wm,
    const float* __restrict__ W1, const float* __restrict__ W2) {
    long i = ((long)blockIdx.x * 256 + threadIdx.x) * 4;
    if (i >= TOTW) return;
    const float* src; long off = i;
    if      (i < OFF_WK) { src = Wq; }
    else if (i < OFF_WV) { src = Wk; off = i - OFF_WK; }
    else if (i < OFF_WM) { src = Wv; off = i - OFF_WV; }
    else if (i < OFF_W1) { src = Wm; off = i - OFF_WM; }
    else if (i < OFF_W2) { src = W1; off = i - OFF_W1; }
    else                 { src = W2; off = i - OFF_W2; }
    float4 w = *(const float4*)(src + off);
    float4 h, l;
    h.x = to_tf32(w.x); l.x = w.x - h.x;
    h.y = to_tf32(w.y); l.y = w.y - h.y;
    h.z = to_tf32(w.z); l.z = w.z - h.z;
    h.w = to_tf32(w.w); l.w = w.w - h.w;
    *(float4*)(g_whi + i) = h;
    *(float4*)(g_wlo + i) = l;
}

// ---------------------------------------------------------------------------
// Tensor-core GEMM (3xTF32), pre-split weights.
// Block tile 64x64x32, 128 threads (4 warps, 2Mx2N, warp tile 32x32).
// grid = (32 [b2*16+ntile], nmat*mtiles, 2 streams).
// Fusions: concat-K, BN+relu on X load, residual epilogue, up to 3 matrices.
// ---------------------------------------------------------------------------
struct GArgs {
    const float* Whi[3];
    const float* Wlo[3];
    const float* bias[3];
    const float* X0[3][2];
    const float* X1[2];
    const float* res[2];
    const float* bnp[2];
    float*       out[3][2];
    int M, K, K0, use_bn, mtiles;
};

__global__ __launch_bounds__(128) void gemm_tc(GArgs a) {
    __shared__ float Ah[64][36], Al[64][36];
    __shared__ float Bh[32][68], Bl[32][68];

    const int s   = blockIdx.z;
    const int jt  = blockIdx.x;
    const int b2  = jt >> 4;
    const int n0  = (jt & 15) << 6;
    const int mat = blockIdx.y / a.mtiles;
    const int m0  = (blockIdx.y % a.mtiles) << 6;
    const int tid = threadIdx.x;
    const int warp = tid >> 5, lane = tid & 31;
    const int wm = (warp >> 1) << 5;   // 0/32
    const int wn = (warp & 1) << 5;    // 0/32
    const int g = lane >> 2, t = lane & 3;

    const int K = a.K, K0 = a.K0, M = a.M;
    const float* __restrict__ Whi = a.Whi[mat];
    const float* __restrict__ Wlo = a.Wlo[mat];
    const float* __restrict__ X0  = a.X0[mat][s];
    const float* __restrict__ X1  = a.X1[s];
    const float* __restrict__ bnp = a.bnp[s];

    float acc[2][4][4];
    #pragma unroll
    for (int mi = 0; mi < 2; mi++)
        #pragma unroll
        for (int ni = 0; ni < 4; ni++)
            #pragma unroll
            for (int r = 0; r < 4; r++) acc[mi][ni][r] = 0.f;

    for (int k0 = 0; k0 < K; k0 += 32) {
        // A: pure copy of pre-split weights (64x32 hi + lo)
        #pragma unroll
        for (int e = tid; e < 512; e += 128) {
            int m  = e >> 3;
            int kq = (e & 7) << 2;
            size_t woff = (size_t)(m0 + m) * K + k0 + kq;
            float4 h4 = *(const float4*)&Whi[woff];
            Ah[m][kq + 0] = h4.x; Ah[m][kq + 1] = h4.y;
            Ah[m][kq + 2] = h4.z; Ah[m][kq + 3] = h4.w;
            float4 l4 = *(const float4*)&Wlo[woff];
            Al[m][kq + 0] = l4.x; Al[m][kq + 1] = l4.y;
            Al[m][kq + 2] = l4.z; Al[m][kq + 3] = l4.w;
        }
        // B: X tile 32x64 with concat + BN/relu, on-the-fly split
        #pragma unroll
        for (int e = tid; e < 512; e += 128) {
            int kk = e >> 4;
            int nq = (e & 15) << 2;
            int k = k0 + kk;
            float4 v;
            if (k < K0) v = *(const float4*)&X0[((size_t)b2 * K0 + k) * NN + n0 + nq];
            else        v = *(const float4*)&X1[((size_t)b2 * (K - K0) + (k - K0)) * NN + n0 + nq];
            float va[4] = {v.x, v.y, v.z, v.w};
            if (a.use_bn) {
                float sc = bnp[2 * k], sh = bnp[2 * k + 1];
                #pragma unroll
                for (int q = 0; q < 4; q++)
                    va[q] = fmaxf(fmaf(va[q], sc, sh), 0.f);
            }
            #pragma unroll
            for (int q = 0; q < 4; q++) {
                float hi = to_tf32(va[q]);
                Bh[kk][nq + q] = hi;
                Bl[kk][nq + q] = va[q] - hi;   // hw truncates on mma input
            }
        }
        __syncthreads();

        #pragma unroll
        for (int kk = 0; kk < 32; kk += 8) {
            unsigned afh[2][4], afl[2][4];
            #pragma unroll
            for (int mi = 0; mi < 2; mi++) {
                int r0 = wm + mi * 16 + g;
                afh[mi][0] = __float_as_uint(Ah[r0    ][kk + t    ]);
                afh[mi][1] = __float_as_uint(Ah[r0 + 8][kk + t    ]);
                afh[mi][2] = __float_as_uint(Ah[r0    ][kk + t + 4]);
                afh[mi][3] = __float_as_uint(Ah[r0 + 8][kk + t + 4]);
                afl[mi][0] = __float_as_uint(Al[r0    ][kk + t    ]);
                afl[mi][1] = __float_as_uint(Al[r0 + 8][kk + t    ]);
                afl[mi][2] = __float_as_uint(Al[r0    ][kk + t + 4]);
                afl[mi][3] = __float_as_uint(Al[r0 + 8][kk + t + 4]);
            }
            unsigned bfh[4][2], bfl[4][2];
            #pragma unroll
            for (int ni = 0; ni < 4; ni++) {
                int c = wn + ni * 8 + g;
                bfh[ni][0] = __float_as_uint(Bh[kk + t    ][c]);
                bfh[ni][1] = __float_as_uint(Bh[kk + t + 4][c]);
                bfl[ni][0] = __float_as_uint(Bl[kk + t    ][c]);
                bfl[ni][1] = __float_as_uint(Bl[kk + t + 4][c]);
            }
            #pragma unroll
            for (int mi = 0; mi < 2; mi++)
                #pragma unroll
                for (int ni = 0; ni < 4; ni++) {
                    MMA_TF32(acc[mi][ni], afh[mi], bfl[ni]);
                    MMA_TF32(acc[mi][ni], afl[mi], bfh[ni]);
                    MMA_TF32(acc[mi][ni], afh[mi], bfh[ni]);
                }
        }
        __syncthreads();
    }

    const float* resp = a.res[s];
    const float* biasp = a.bias[mat];
    float* outp = a.out[mat][s];
    #pragma unroll
    for (int mi = 0; mi < 2; mi++) {
        #pragma unroll
        for (int half = 0; half < 2; half++) {
            int m = m0 + wm + mi * 16 + g + half * 8;
            float bb = biasp[m];
            #pragma unroll
            for (int ni = 0; ni < 4; ni++) {
                int col = n0 + wn + ni * 8 + 2 * t;
                size_t off = ((size_t)b2 * M + m) * NN + col;
                float2 c;
                c.x = acc[mi][ni][2 * half + 0] + bb;
                c.y = acc[mi][ni][2 * half + 1] + bb;
                if (resp) {
                    float2 r = *(const float2*)(resp + off);
                    c.x += r.x; c.y += r.y;
                }
                *(float2*)(outp + off) = c;
            }
        }
    }
}

// ---------------------------------------------------------------------------
// Flash-style attention (unchanged from round 3).
// ---------------------------------------------------------------------------
#define ATTN_SMEM (4 * 64 * 68 * 4)

__global__ __launch_bounds__(256) void attn_kernel() {
    extern __shared__ __align__(16) float sm[];
    float (*Qs)[68] = (float(*)[68])(sm);
    float (*Ks)[68] = (float(*)[68])(sm + 64 * 68);
    float (*Vs)[68] = (float(*)[68])(sm + 2 * 64 * 68);
    float (*Ps)[68] = (float(*)[68])(sm + 3 * 64 * 68);

    const int qt = blockIdx.x;
    const int bh = blockIdx.y;
    const int s  = blockIdx.z;
    const int b2 = bh >> 2, h = bh & 3;
    const int q0 = qt << 6;
    const int tid = threadIdx.x;
    const int tx = tid & 15, ty = tid >> 4;

    size_t base = (size_t)s * TEN + (size_t)b2 * (DD * NN);
    const float* __restrict__ qp = g_q + base;
    const float* __restrict__ kp = g_k + base;
    const float* __restrict__ vp = g_v + base;
    float* mp = g_msg + base;

    for (int e = tid; e < 4096; e += 256) {
        int qi = e & 63, d = e >> 6;
        Qs[d][qi] = qp[(size_t)(d * 4 + h) * NN + q0 + qi] * 0.125f;
    }

    float o[4][4] = {};
    float mi[4], li[4];
    #pragma unroll
    for (int i = 0; i < 4; i++) { mi[i] = -1e30f; li[i] = 0.f; }

    for (int kt = 0; kt < 16; kt++) {
        int m0k = kt << 6;
        __syncthreads();
        for (int e = tid; e < 4096; e += 256) {
            int kk = e & 63, d = e >> 6;
            float kv = kp[(size_t)(d * 4 + h) * NN + m0k + kk];
            float vv = vp[(size_t)(d * 4 + h) * NN + m0k + kk];
            Ks[d][kk] = kv;
            Vs[kk][d] = vv;
        }
        __syncthreads();

        float sreg[4][4] = {};
        #pragma unroll 8
        for (int d = 0; d < 64; d++) {
            float4 qv = *(const float4*)&Qs[d][ty * 4];
            float4 kv = *(const float4*)&Ks[d][tx * 4];
            float qa[4] = {qv.x, qv.y, qv.z, qv.w};
            float ka[4] = {kv.x, kv.y, kv.z, kv.w};
            #pragma unroll
            for (int i = 0; i < 4; i++)
                #pragma unroll
                for (int j = 0; j < 4; j++)
                    sreg[i][j] = fmaf(qa[i], ka[j], sreg[i][j]);
        }

        #pragma unroll
        for (int i = 0; i < 4; i++) {
            float rm = fmaxf(fmaxf(sreg[i][0], sreg[i][1]),
                             fmaxf(sreg[i][2], sreg[i][3]));
            rm = fmaxf(rm, __shfl_xor_sync(0xffffffffu, rm, 1));
            rm = fmaxf(rm, __shfl_xor_sync(0xffffffffu, rm, 2));
            rm = fmaxf(rm, __shfl_xor_sync(0xffffffffu, rm, 4));
            rm = fmaxf(rm, __shfl_xor_sync(0xffffffffu, rm, 8));
            float mn = fmaxf(mi[i], rm);
            float alpha = __expf(mi[i] - mn);
            mi[i] = mn;
            float rs = 0.f;
            #pragma unroll
            for (int j = 0; j < 4; j++) {
                float p = __expf(sreg[i][j] - mn);
                sreg[i][j] = p;
                rs += p;
            }
            rs += __shfl_xor_sync(0xffffffffu, rs, 1);
            rs += __shfl_xor_sync(0xffffffffu, rs, 2);
            rs += __shfl_xor_sync(0xffffffffu, rs, 4);
            rs += __shfl_xor_sync(0xffffffffu, rs, 8);
            li[i] = li[i] * alpha + rs;
            #pragma unroll
            for (int j = 0; j < 4; j++) o[i][j] *= alpha;
        }

        #pragma unroll
        for (int i = 0; i < 4; i++)
            #pragma unroll
            for (int j = 0; j < 4; j++)
                Ps[tx * 4 + j][ty * 4 + i] = sreg[i][j];
        __syncthreads();

        #pragma unroll 8
        for (int kk = 0; kk < 64; kk++) {
            float4 pv = *(const float4*)&Ps[kk][ty * 4];
            float4 vv = *(const float4*)&Vs[kk][tx * 4];
            float pa[4] = {pv.x, pv.y, pv.z, pv.w};
            float va[4] = {vv.x, vv.y, vv.z, vv.w};
            #pragma unroll
            for (int i = 0; i < 4; i++)
                #pragma unroll
                for (int j = 0; j < 4; j++)
                    o[i][j] = fmaf(pa[i], va[j], o[i][j]);
        }
    }

    float inv[4];
    #pragma unroll
    for (int i = 0; i < 4; i++) inv[i] = 1.f / li[i];
    __syncthreads();
    #pragma unroll
    for (int i = 0; i < 4; i++)
        #pragma unroll
        for (int j = 0; j < 4; j++)
            Ps[tx * 4 + j][ty * 4 + i] = o[i][j] * inv[i];
    __syncthreads();
    for (int e = tid; e < 4096; e += 256) {
        int qi = e & 63, d = e >> 6;
        mp[(size_t)(d * 4 + h) * NN + q0 + qi] = Ps[d][qi];
    }
}

// ---------------------------------------------------------------------------
// BatchNorm stats (unchanged).
// ---------------------------------------------------------------------------
__global__ __launch_bounds__(256) void bn_stats_kernel(const float* __restrict__ g1,
                                                       const float* __restrict__ be1) {
    const int c = blockIdx.x;
    const int s = blockIdx.y;
    const float* hp = g_h + (size_t)s * HTEN;
    int tid = threadIdx.x;
    float sum = 0.f, sq = 0.f;
    for (int idx = tid; idx < 2048; idx += 256) {
        int b2 = idx >> 10, n = idx & 1023;
        float v = hp[((size_t)b2 * 512 + c) * NN + n];
        sum += v;
        sq = fmaf(v, v, sq);
    }
    #pragma unroll
    for (int w = 16; w; w >>= 1) {
        sum += __shfl_xor_sync(0xffffffffu, sum, w);
        sq  += __shfl_xor_sync(0xffffffffu, sq,  w);
    }
    __shared__ float ssum[8], ssq[8];
    int wid = tid >> 5, lane = tid & 31;
    if (lane == 0) { ssum[wid] = sum; ssq[wid] = sq; }
    __syncthreads();
    if (tid == 0) {
        float S = 0.f, Q = 0.f;
        #pragma unroll
        for (int i = 0; i < 8; i++) { S += ssum[i]; Q += ssq[i]; }
        float mean = S * (1.f / 2048.f);
        float var  = Q * (1.f / 2048.f) - mean * mean;
        float rstd = rsqrtf(var + 1e-5f);
        float sc = rstd * g1[c];
        float sh = be1[c] - mean * sc;
        g_stats[(s * 512 + c) * 2 + 0] = sc;
        g_stats[(s * 512 + c) * 2 + 1] = sh;
    }
}

// ---------------------------------------------------------------------------
// Host orchestration
// ---------------------------------------------------------------------------
extern "C" void kernel_launch(void* const* d_in, const int* in_sizes, int n_in,
                              void* d_out, int out_size) {
    const float* desc0 = (const float*)d_in[0];
    const float* desc1 = (const float*)d_in[1];
    const float* Wq  = (const float*)d_in[2];
    const float* bq  = (const float*)d_in[3];
    const float* Wk  = (const float*)d_in[4];
    const float* bk  = (const float*)d_in[5];
    const float* Wv  = (const float*)d_in[6];
    const float* bv  = (const float*)d_in[7];
    const float* Wm  = (const float*)d_in[8];
    const float* bm  = (const float*)d_in[9];
    const float* W1  = (const float*)d_in[10];
    const float* b1  = (const float*)d_in[11];
    const float* g1  = (const float*)d_in[12];
    const float* be1 = (const float*)d_in[13];
    const float* W2  = (const float*)d_in[14];
    const float* b2  = (const float*)d_in[15];
    float* out = (float*)d_out;

    float *qb, *kb, *vb, *msgb, *mmb, *hb, *statsb, *whi, *wlo;
    cudaGetSymbolAddress((void**)&qb,    g_q);
    cudaGetSymbolAddress((void**)&kb,    g_k);
    cudaGetSymbolAddress((void**)&vb,    g_v);
    cudaGetSymbolAddress((void**)&msgb,  g_msg);
    cudaGetSymbolAddress((void**)&mmb,   g_mm);
    cudaGetSymbolAddress((void**)&hb,    g_h);
    cudaGetSymbolAddress((void**)&statsb, g_stats);
    cudaGetSymbolAddress((void**)&whi,   g_whi);
    cudaGetSymbolAddress((void**)&wlo,   g_wlo);

    cudaFuncSetAttribute(attn_kernel,
                         cudaFuncAttributeMaxDynamicSharedMemorySize, ATTN_SMEM);

    // pre-split all weights into hi/lo
    presplit_kernel<<<(int)((TOTW / 4 + 255) / 256), 256>>>(Wq, Wk, Wv, Wm, W1, W2);

    // outs[2] = desc0, outs[3] = desc1 (faithful quirk)
    cudaMemcpyAsync(out + 2 * (size_t)TEN, desc0, TEN * sizeof(float),
                    cudaMemcpyDeviceToDevice, 0);
    cudaMemcpyAsync(out + 3 * (size_t)TEN, desc1, TEN * sizeof(float),
                    cudaMemcpyDeviceToDevice, 0);

    const float* xa = desc0;
    const float* xb = desc1;

    for (int i = 0; i < 18; i++) {
        const float *sa, *sb, *ra, *rb;
        float *oa, *ob;
        if (i == 0) {
            sa = xa; sb = xb; ra = desc0; rb = desc1;
            oa = out;            ob = out + (size_t)TEN;
        } else if (i == 1) {
            sa = xb; sb = xa; ra = desc0; rb = desc1;
            oa = out + 4 * (size_t)TEN; ob = out + 5 * (size_t)TEN;
        } else {
            if ((i & 1) == 0) { sa = xa; sb = xb; }
            else              { sa = xb; sb = xa; }
            ra = xa; rb = xb;
            oa = out + (size_t)(2 + 2 * i) * TEN;
            ob = oa + (size_t)TEN;
        }

        const float* Wq_hi = whi + OFF_WQ + (size_t)i * 65536;
        const float* Wq_lo = wlo + OFF_WQ + (size_t)i * 65536;
        const float* Wk_hi = whi + OFF_WK + (size_t)i * 65536;
        const float* Wk_lo = wlo + OFF_WK + (size_t)i * 65536;
        const float* Wv_hi = whi + OFF_WV + (size_t)i * 65536;
        const float* Wv_lo = wlo + OFF_WV + (size_t)i * 65536;
        const float* Wm_hi = whi + OFF_WM + (size_t)i * 65536;
        const float* Wm_lo = wlo + OFF_WM + (size_t)i * 65536;
        const float* W1_hi = whi + OFF_W1 + (size_t)i * 262144;
        const float* W1_lo = wlo + OFF_W1 + (size_t)i * 262144;
        const float* W2_hi = whi + OFF_W2 + (size_t)i * 131072;
        const float* W2_lo = wlo + OFF_W2 + (size_t)i * 131072;
        const float* bq_i = bq + (size_t)i * 256;
        const float* bk_i = bk + (size_t)i * 256;
        const float* bv_i = bv + (size_t)i * 256;
        const float* bm_i = bm + (size_t)i * 256;
        const float* b1_i = b1 + (size_t)i * 512;
        const float* b2_i = b2 + (size_t)i * 256;
        const float* g1_i = g1 + (size_t)i * 512;
        const float* be_i = be1 + (size_t)i * 512;

        GArgs ga = {};
        ga.bnp[0] = statsb; ga.bnp[1] = statsb + 1024;

        // --- q/k/v (merged, 3 matrices) ---
        ga.Whi[0] = Wq_hi; ga.Wlo[0] = Wq_lo; ga.bias[0] = bq_i;
        ga.Whi[1] = Wk_hi; ga.Wlo[1] = Wk_lo; ga.bias[1] = bk_i;
        ga.Whi[2] = Wv_hi; ga.Wlo[2] = Wv_lo; ga.bias[2] = bv_i;
        ga.X0[0][0] = xa; ga.X0[0][1] = xb;
        ga.X0[1][0] = sa; ga.X0[1][1] = sb;
        ga.X0[2][0] = sa; ga.X0[2][1] = sb;
        ga.out[0][0] = qb; ga.out[0][1] = qb + TEN;
        ga.out[1][0] = kb; ga.out[1][1] = kb + TEN;
        ga.out[2][0] = vb; ga.out[2][1] = vb + TEN;
        ga.X1[0] = ga.X1[1] = nullptr;
        ga.res[0] = ga.res[1] = nullptr;
        ga.M = 256; ga.K = 256; ga.K0 = 256; ga.use_bn = 0; ga.mtiles = 4;
        gemm_tc<<<dim3(32, 12, 2), 128>>>(ga);

        // --- attention ---
        attn_kernel<<<dim3(16, 8, 2), 256, ATTN_SMEM>>>();

        // --- msg projection ---
        ga.Whi[0] = Wm_hi; ga.Wlo[0] = Wm_lo; ga.bias[0] = bm_i;
        ga.X0[0][0] = msgb; ga.X0[0][1] = msgb + TEN;
        ga.out[0][0] = mmb; ga.out[0][1] = mmb + TEN;
        ga.M = 256; ga.K = 256; ga.K0 = 256; ga.use_bn = 0; ga.mtiles = 4;
        gemm_tc<<<dim3(32, 4, 2), 128>>>(ga);

        // --- h = W1 [x; msg] + b1 ---
        ga.Whi[0] = W1_hi; ga.Wlo[0] = W1_lo; ga.bias[0] = b1_i;
        ga.X0[0][0] = xa; ga.X0[0][1] = xb;
        ga.X1[0] = mmb; ga.X1[1] = mmb + TEN;
        ga.out[0][0] = hb; ga.out[0][1] = hb + HTEN;
        ga.M = 512; ga.K = 512; ga.K0 = 256; ga.use_bn = 0; ga.mtiles = 8;
        gemm_tc<<<dim3(32, 8, 2), 128>>>(ga);

        // --- BN stats ---
        bn_stats_kernel<<<dim3(512, 2), 256>>>(g1_i, be_i);

        // --- out = res + W2 relu(BN(h)) + b2 ---
        ga.Whi[0] = W2_hi; ga.Wlo[0] = W2_lo; ga.bias[0] = b2_i;
        ga.X0[0][0] = hb; ga.X0[0][1] = hb + HTEN;
        ga.X1[0] = ga.X1[1] = nullptr;
        ga.res[0] = ra; ga.res[1] = rb;
        ga.out[0][0] = oa; ga.out[0][1] = ob;
        ga.M = 256; ga.K = 512; ga.K0 = 512; ga.use_bn = 1; ga.mtiles = 4;
        gemm_tc<<<dim3(32, 4, 2), 128>>>(ga);
        ga.res[0] = ga.res[1] = nullptr;

        xa = oa; xb = ob;
    }
}

// round 5
// speedup vs baseline: 1.4945x; 1.0734x over previous
#include <cuda_runtime.h>
#include <math.h>

// ---------------------------------------------------------------------------
// AttentionalGNN: L=18 layers, D=256, H=4 (head dim 64), B=2, N=1024.
// Activations: [b2][C][N] fp32, channel c = d*4 + h.
// Round 5: attention moved to tensor cores (3xTF32 QK^T and PV) with
// polynomial exp on the FMA pipe. GEMMs unchanged from round 4.
// ---------------------------------------------------------------------------

#define BB   2
#define DD   256
#define NN   1024
#define TEN  (BB*DD*NN)
#define HTEN (BB*512*NN)

// Scratch (device globals). [stream][b2][C][N]
__device__ float g_q  [2*TEN];
__device__ float g_k  [2*TEN];
__device__ float g_v  [2*TEN];
__device__ float g_msg[2*TEN];
__device__ float g_mm [2*TEN];
__device__ float g_h  [2*HTEN];
__device__ float g_stats[2*512*2];

// Pre-split weights (hi/lo), concatenated: Wq|Wk|Wv|Wm|W1|W2
#define SZ_D  (18L*256*256)
#define SZ_1  (18L*512*512)
#define SZ_2  (18L*256*512)
#define OFF_WQ 0L
#define OFF_WK (SZ_D)
#define OFF_WV (2*SZ_D)
#define OFF_WM (3*SZ_D)
#define OFF_W1 (4*SZ_D)
#define OFF_W2 (4*SZ_D + SZ_1)
#define TOTW   (4*SZ_D + SZ_1 + SZ_2)
__device__ float g_whi[TOTW];
__device__ float g_wlo[TOTW];

__device__ __forceinline__ float to_tf32(float x) {
    unsigned u;
    asm("cvt.rna.tf32.f32 %0, %1;" : "=r"(u) : "f"(x));
    return __uint_as_float(u);
}

#define MMA_TF32(acc, af, bf)                                                  \
    asm volatile(                                                              \
        "mma.sync.aligned.m16n8k8.row.col.f32.tf32.tf32.f32 "                  \
        "{%0,%1,%2,%3}, {%4,%5,%6,%7}, {%8,%9}, {%0,%1,%2,%3};"                \
        : "+f"(acc[0]), "+f"(acc[1]), "+f"(acc[2]), "+f"(acc[3])               \
        : "r"(af[0]), "r"(af[1]), "r"(af[2]), "r"(af[3]),                      \
          "r"(bf[0]), "r"(bf[1]))

// exp on the FMA pipe: round-to-int trick + 2^f Taylor (deg 6), rel err ~2e-7.
// Valid for x <= 0 (we clamp below -80).
__device__ __forceinline__ float expq(float x) {
    x = fmaxf(x, -80.f);
    float t = fmaf(x, 1.4426950408889634f, 12582912.f);   // n = round(x*log2e)
    float n = t - 12582912.f;
    float f = fmaf(x, 1.4426950408889634f, -n);           // f in [-0.5, 0.5]
    float p = 0.0001540353039338161f;
    p = fmaf(p, f, 0.0013333558146428443f);
    p = fmaf(p, f, 0.009618129107628477f);
    p = fmaf(p, f, 0.05550410866482158f);
    p = fmaf(p, f, 0.2402265069591007f);
    p = fmaf(p, f, 0.6931471805599453f);
    p = fmaf(p, f, 1.0f);
    int ni = __float_as_int(t) - 0x4B400000;              // integer n
    return __int_as_float(__float_as_int(p) + (ni << 23));
}

// ---------------------------------------------------------------------------
// Weight pre-split
// ---------------------------------------------------------------------------
__global__ __launch_bounds__(256) void presplit_kernel(
    const float* __restrict__ Wq, const float* __restrict__ Wk,
    const float* __restrict__ Wv, const float* __restrict__ Wm,
    const float* __restrict__ W1, const float* __restrict__ W2) {
    long i = ((long)blockIdx.x * 256 + threadIdx.x) * 4;
    if (i >= TOTW) return;
    const float* src; long off = i;
    if      (i < OFF_WK) { src = Wq; }
    else if (i < OFF_WV) { src = Wk; off = i - OFF_WK; }
    else if (i < OFF_WM) { src = Wv; off = i - OFF_WV; }
    else if (i < OFF_W1) { src = Wm; off = i - OFF_WM; }
    else if (i < OFF_W2) { src = W1; off = i - OFF_W1; }
    else                 { src = W2; off = i - OFF_W2; }
    float4 w = *(const float4*)(src + off);
    float4 h, l;
    h.x = to_tf32(w.x); l.x = w.x - h.x;
    h.y = to_tf32(w.y); l.y = w.y - h.y;
    h.z = to_tf32(w.z); l.z = w.z - h.z;
    h.w = to_tf32(w.w); l.w = w.w - h.w;
    *(float4*)(g_whi + i) = h;
    *(float4*)(g_wlo + i) = l;
}

// ---------------------------------------------------------------------------
// Tensor-core GEMM (3xTF32), pre-split weights (unchanged from round 4).
// ---------------------------------------------------------------------------
struct GArgs {
    const float* Whi[3];
    const float* Wlo[3];
    const float* bias[3];
    const float* X0[3][2];
    const float* X1[2];
    const float* res[2];
    const float* bnp[2];
    float*       out[3][2];
    int M, K, K0, use_bn, mtiles;
};

__global__ __launch_bounds__(128) void gemm_tc(GArgs a) {
    __shared__ float Ah[64][36], Al[64][36];
    __shared__ float Bh[32][68], Bl[32][68];

    const int s   = blockIdx.z;
    const int jt  = blockIdx.x;
    const int b2  = jt >> 4;
    const int n0  = (jt & 15) << 6;
    const int mat = blockIdx.y / a.mtiles;
    const int m0  = (blockIdx.y % a.mtiles) << 6;
    const int tid = threadIdx.x;
    const int warp = tid >> 5, lane = tid & 31;
    const int wm = (warp >> 1) << 5;
    const int wn = (warp & 1) << 5;
    const int g = lane >> 2, t = lane & 3;

    const int K = a.K, K0 = a.K0, M = a.M;
    const float* __restrict__ Whi = a.Whi[mat];
    const float* __restrict__ Wlo = a.Wlo[mat];
    const float* __restrict__ X0  = a.X0[mat][s];
    const float* __restrict__ X1  = a.X1[s];
    const float* __restrict__ bnp = a.bnp[s];

    float acc[2][4][4];
    #pragma unroll
    for (int mi = 0; mi < 2; mi++)
        #pragma unroll
        for (int ni = 0; ni < 4; ni++)
            #pragma unroll
            for (int r = 0; r < 4; r++) acc[mi][ni][r] = 0.f;

    for (int k0 = 0; k0 < K; k0 += 32) {
        #pragma unroll
        for (int e = tid; e < 512; e += 128) {
            int m  = e >> 3;
            int kq = (e & 7) << 2;
            size_t woff = (size_t)(m0 + m) * K + k0 + kq;
            float4 h4 = *(const float4*)&Whi[woff];
            Ah[m][kq + 0] = h4.x; Ah[m][kq + 1] = h4.y;
            Ah[m][kq + 2] = h4.z; Ah[m][kq + 3] = h4.w;
            float4 l4 = *(const float4*)&Wlo[woff];
            Al[m][kq + 0] = l4.x; Al[m][kq + 1] = l4.y;
            Al[m][kq + 2] = l4.z; Al[m][kq + 3] = l4.w;
        }
        #pragma unroll
        for (int e = tid; e < 512; e += 128) {
            int kk = e >> 4;
            int nq = (e & 15) << 2;
            int k = k0 + kk;
            float4 v;
            if (k < K0) v = *(const float4*)&X0[((size_t)b2 * K0 + k) * NN + n0 + nq];
            else        v = *(const float4*)&X1[((size_t)b2 * (K - K0) + (k - K0)) * NN + n0 + nq];
            float va[4] = {v.x, v.y, v.z, v.w};
            if (a.use_bn) {
                float sc = bnp[2 * k], sh = bnp[2 * k + 1];
                #pragma unroll
                for (int q = 0; q < 4; q++)
                    va[q] = fmaxf(fmaf(va[q], sc, sh), 0.f);
            }
            #pragma unroll
            for (int q = 0; q < 4; q++) {
                float hi = to_tf32(va[q]);
                Bh[kk][nq + q] = hi;
                Bl[kk][nq + q] = va[q] - hi;
            }
        }
        __syncthreads();

        #pragma unroll
        for (int kk = 0; kk < 32; kk += 8) {
            unsigned afh[2][4], afl[2][4];
            #pragma unroll
            for (int mi = 0; mi < 2; mi++) {
                int r0 = wm + mi * 16 + g;
                afh[mi][0] = __float_as_uint(Ah[r0    ][kk + t    ]);
                afh[mi][1] = __float_as_uint(Ah[r0 + 8][kk + t    ]);
                afh[mi][2] = __float_as_uint(Ah[r0    ][kk + t + 4]);
                afh[mi][3] = __float_as_uint(Ah[r0 + 8][kk + t + 4]);
                afl[mi][0] = __float_as_uint(Al[r0    ][kk + t    ]);
                afl[mi][1] = __float_as_uint(Al[r0 + 8][kk + t    ]);
                afl[mi][2] = __float_as_uint(Al[r0    ][kk + t + 4]);
                afl[mi][3] = __float_as_uint(Al[r0 + 8][kk + t + 4]);
            }
            unsigned bfh[4][2], bfl[4][2];
            #pragma unroll
            for (int ni = 0; ni < 4; ni++) {
                int c = wn + ni * 8 + g;
                bfh[ni][0] = __float_as_uint(Bh[kk + t    ][c]);
                bfh[ni][1] = __float_as_uint(Bh[kk + t + 4][c]);
                bfl[ni][0] = __float_as_uint(Bl[kk + t    ][c]);
                bfl[ni][1] = __float_as_uint(Bl[kk + t + 4][c]);
            }
            #pragma unroll
            for (int mi = 0; mi < 2; mi++)
                #pragma unroll
                for (int ni = 0; ni < 4; ni++) {
                    MMA_TF32(acc[mi][ni], afh[mi], bfl[ni]);
                    MMA_TF32(acc[mi][ni], afl[mi], bfh[ni]);
                    MMA_TF32(acc[mi][ni], afh[mi], bfh[ni]);
                }
        }
        __syncthreads();
    }

    const float* resp = a.res[s];
    const float* biasp = a.bias[mat];
    float* outp = a.out[mat][s];
    #pragma unroll
    for (int mi = 0; mi < 2; mi++) {
        #pragma unroll
        for (int half = 0; half < 2; half++) {
            int m = m0 + wm + mi * 16 + g + half * 8;
            float bb = biasp[m];
            #pragma unroll
            for (int ni = 0; ni < 4; ni++) {
                int col = n0 + wn + ni * 8 + 2 * t;
                size_t off = ((size_t)b2 * M + m) * NN + col;
                float2 c;
                c.x = acc[mi][ni][2 * half + 0] + bb;
                c.y = acc[mi][ni][2 * half + 1] + bb;
                if (resp) {
                    float2 r = *(const float2*)(resp + off);
                    c.x += r.x; c.y += r.y;
                }
                *(float2*)(outp + off) = c;
            }
        }
    }
}

// ---------------------------------------------------------------------------
// Tensor-core flash attention (3xTF32). Block = (qtile 64, b2*4+h, stream),
// 256 threads = 8 warps. S phase: warps (qw 0-3, kw 0-1), 16q x 32k each.
// PV phase: warps (qw 0-3, dw 0-1), 16q x 32d each, full 64k.
// Dyn smem: Qs,Ks,Vs,Ph,Pl = 5 * 64*68*4 = 87040 B  (2 blocks/SM).
// ---------------------------------------------------------------------------
#define ATTN_SMEM (5 * 64 * 68 * 4)

__global__ __launch_bounds__(256) void attn_kernel() {
    extern __shared__ __align__(16) float sm[];
    float (*Qs)[68] = (float(*)[68])(sm);              // [d][q] (scaled)
    float (*Ks)[68] = (float(*)[68])(sm + 64 * 68);    // [d][k]
    float (*Vs)[68] = (float(*)[68])(sm + 2 * 64 * 68);// [k][d]
    float (*Ph)[68] = (float(*)[68])(sm + 3 * 64 * 68);// [q][k] hi, then [d][q] out
    float (*Pl)[68] = (float(*)[68])(sm + 4 * 64 * 68);// [q][k] lo
    __shared__ float red_max[2][4][16];
    __shared__ float red_sum[2][4][16];

    const int qt = blockIdx.x;
    const int bh = blockIdx.y;
    const int s  = blockIdx.z;
    const int b2 = bh >> 2, h = bh & 3;
    const int q0 = qt << 6;
    const int tid = threadIdx.x;
    const int warp = tid >> 5, lane = tid & 31;
    const int g = lane >> 2, t = lane & 3;
    const int qw = warp >> 1, kw = warp & 1;
    const int qcol = qw << 4;        // warp q base (rows of S / O)
    const int kcol = kw << 5;        // warp k base (S) == warp d base (PV)

    size_t base = (size_t)s * TEN + (size_t)b2 * (DD * NN);
    const float* __restrict__ qp = g_q + base;
    const float* __restrict__ kp = g_k + base;
    const float* __restrict__ vp = g_v + base;
    float* mp = g_msg + base;

    // load Q tile [d][q], fold 1/8 scale
    for (int e = tid; e < 4096; e += 256) {
        int qi = e & 63, d = e >> 6;
        Qs[d][qi] = qp[(size_t)(d * 4 + h) * NN + q0 + qi] * 0.125f;
    }

    float oacc[4][4] = {};
    float mi2[2] = {-1e30f, -1e30f};
    float li2[2] = {0.f, 0.f};

    for (int kt = 0; kt < 16; kt++) {
        int m0k = kt << 6;
        __syncthreads();   // prev PV done reading Ks/Vs/Ph/Pl
        for (int e = tid; e < 4096; e += 256) {
            int kk = e & 63, d = e >> 6;
            size_t goff = (size_t)(d * 4 + h) * NN + m0k + kk;
            Ks[d][kk] = kp[goff];
            Vs[kk][d] = vp[goff];
        }
        __syncthreads();

        // ----- S = Q^T K (3xTF32), warp tile 16q x 32k -----
        float sacc[4][4] = {};
        #pragma unroll
        for (int kk = 0; kk < 64; kk += 8) {
            float av[4];
            av[0] = Qs[kk + t    ][qcol + g    ];
            av[1] = Qs[kk + t    ][qcol + g + 8];
            av[2] = Qs[kk + t + 4][qcol + g    ];
            av[3] = Qs[kk + t + 4][qcol + g + 8];
            unsigned ah[4], al[4];
            #pragma unroll
            for (int j = 0; j < 4; j++) {
                float hi = to_tf32(av[j]);
                ah[j] = __float_as_uint(hi);
                al[j] = __float_as_uint(av[j] - hi);
            }
            #pragma unroll
            for (int ni = 0; ni < 4; ni++) {
                int c = kcol + ni * 8 + g;
                float b0 = Ks[kk + t    ][c];
                float b1 = Ks[kk + t + 4][c];
                float h0 = to_tf32(b0), h1 = to_tf32(b1);
                unsigned bh2[2] = {__float_as_uint(h0), __float_as_uint(h1)};
                unsigned bl2[2] = {__float_as_uint(b0 - h0), __float_as_uint(b1 - h1)};
                MMA_TF32(sacc[ni], ah, bl2);
                MMA_TF32(sacc[ni], al, bh2);
                MMA_TF32(sacc[ni], ah, bh2);
            }
        }

        // ----- online softmax -----
        // rows: r=0 -> qcol+g (regs [ni][0..1]); r=1 -> qcol+g+8 (regs [ni][2..3])
        float mloc[2] = {-1e30f, -1e30f};
        #pragma unroll
        for (int ni = 0; ni < 4; ni++) {
            mloc[0] = fmaxf(mloc[0], fmaxf(sacc[ni][0], sacc[ni][1]));
            mloc[1] = fmaxf(mloc[1], fmaxf(sacc[ni][2], sacc[ni][3]));
        }
        #pragma unroll
        for (int r = 0; r < 2; r++) {
            mloc[r] = fmaxf(mloc[r], __shfl_xor_sync(0xffffffffu, mloc[r], 1));
            mloc[r] = fmaxf(mloc[r], __shfl_xor_sync(0xffffffffu, mloc[r], 2));
        }
        if (t == 0) {
            red_max[kw][qw][g    ] = mloc[0];
            red_max[kw][qw][g + 8] = mloc[1];
        }
        __syncthreads();
        float mn[2], alpha[2];
        #pragma unroll
        for (int r = 0; r < 2; r++) {
            int row = g + r * 8;
            float mk = fmaxf(red_max[0][qw][row], red_max[1][qw][row]);
            mn[r] = fmaxf(mi2[r], mk);
            alpha[r] = expq(mi2[r] - mn[r]);
            mi2[r] = mn[r];
        }
        float rs[2] = {0.f, 0.f};
        #pragma unroll
        for (int ni = 0; ni < 4; ni++) {
            #pragma unroll
            for (int j = 0; j < 4; j++) {
                int r = j >> 1;
                float p = expq(sacc[ni][j] - mn[r]);
                sacc[ni][j] = p;
                rs[r] += p;
            }
        }
        #pragma unroll
        for (int r = 0; r < 2; r++) {
            rs[r] += __shfl_xor_sync(0xffffffffu, rs[r], 1);
            rs[r] += __shfl_xor_sync(0xffffffffu, rs[r], 2);
        }
        if (t == 0) {
            red_sum[kw][qw][g    ] = rs[0];
            red_sum[kw][qw][g + 8] = rs[1];
        }
        // stage P hi/lo to smem [q][k]
        #pragma unroll
        for (int ni = 0; ni < 4; ni++) {
            #pragma unroll
            for (int r = 0; r < 2; r++) {
                int row = qcol + g + r * 8;
                int col = kcol + ni * 8 + 2 * t;
                float p0 = sacc[ni][2 * r], p1 = sacc[ni][2 * r + 1];
                float h0 = to_tf32(p0), h1 = to_tf32(p1);
                float2 ph = make_float2(h0, h1);
                float2 pl = make_float2(p0 - h0, p1 - h1);
                *(float2*)&Ph[row][col] = ph;
                *(float2*)&Pl[row][col] = pl;
            }
        }
        __syncthreads();
        #pragma unroll
        for (int r = 0; r < 2; r++) {
            int row = g + r * 8;
            float rstot = red_sum[0][qw][row] + red_sum[1][qw][row];
            li2[r] = li2[r] * alpha[r] + rstot;
        }
        // rescale O
        #pragma unroll
        for (int ni = 0; ni < 4; ni++) {
            oacc[ni][0] *= alpha[0]; oacc[ni][1] *= alpha[0];
            oacc[ni][2] *= alpha[1]; oacc[ni][3] *= alpha[1];
        }

        // ----- O += P V (3xTF32), warp tile 16q x 32d, full 64 k -----
        #pragma unroll
        for (int kk = 0; kk < 64; kk += 8) {
            unsigned ah[4], al[4];
            ah[0] = __float_as_uint(Ph[qcol + g    ][kk + t    ]);
            ah[1] = __float_as_uint(Ph[qcol + g + 8][kk + t    ]);
            ah[2] = __float_as_uint(Ph[qcol + g    ][kk + t + 4]);
            ah[3] = __float_as_uint(Ph[qcol + g + 8][kk + t + 4]);
            al[0] = __float_as_uint(Pl[qcol + g    ][kk + t    ]);
            al[1] = __float_as_uint(Pl[qcol + g + 8][kk + t    ]);
            al[2] = __float_as_uint(Pl[qcol + g    ][kk + t + 4]);
            al[3] = __float_as_uint(Pl[qcol + g + 8][kk + t + 4]);
            #pragma unroll
            for (int ni = 0; ni < 4; ni++) {
                int c = kcol + ni * 8 + g;   // d column
                float b0 = Vs[kk + t    ][c];
                float b1 = Vs[kk + t + 4][c];
                float h0 = to_tf32(b0), h1 = to_tf32(b1);
                unsigned bh2[2] = {__float_as_uint(h0), __float_as_uint(h1)};
                unsigned bl2[2] = {__float_as_uint(b0 - h0), __float_as_uint(b1 - h1)};
                MMA_TF32(oacc[ni], ah, bl2);
                MMA_TF32(oacc[ni], al, bh2);
                MMA_TF32(oacc[ni], ah, bh2);
            }
        }
    }

    float inv[2] = {1.f / li2[0], 1.f / li2[1]};
    __syncthreads();   // all PV reads of Ph done; reuse as [d][q] staging
    #pragma unroll
    for (int ni = 0; ni < 4; ni++) {
        #pragma unroll
        for (int j = 0; j < 4; j++) {
            int r = j >> 1;
            int row_q = qcol + g + r * 8;
            int col_d = kcol + ni * 8 + 2 * t + (j & 1);
            Ph[col_d][row_q] = oacc[ni][j] * inv[r];
        }
    }
    __syncthreads();
    for (int e = tid; e < 4096; e += 256) {
        int qi = e & 63, d = e >> 6;
        mp[(size_t)(d * 4 + h) * NN + q0 + qi] = Ph[d][qi];
    }
}

// ---------------------------------------------------------------------------
// BatchNorm stats (unchanged).
// ---------------------------------------------------------------------------
__global__ __launch_bounds__(256) void bn_stats_kernel(const float* __restrict__ g1,
                                                       const float* __restrict__ be1) {
    const int c = blockIdx.x;
    const int s = blockIdx.y;
    const float* hp = g_h + (size_t)s * HTEN;
    int tid = threadIdx.x;
    float sum = 0.f, sq = 0.f;
    for (int idx = tid; idx < 2048; idx += 256) {
        int b2 = idx >> 10, n = idx & 1023;
        float v = hp[((size_t)b2 * 512 + c) * NN + n];
        sum += v;
        sq = fmaf(v, v, sq);
    }
    #pragma unroll
    for (int w = 16; w; w >>= 1) {
        sum += __shfl_xor_sync(0xffffffffu, sum, w);
        sq  += __shfl_xor_sync(0xffffffffu, sq,  w);
    }
    __shared__ float ssum[8], ssq[8];
    int wid = tid >> 5, lane = tid & 31;
    if (lane == 0) { ssum[wid] = sum; ssq[wid] = sq; }
    __syncthreads();
    if (tid == 0) {
        float S = 0.f, Q = 0.f;
        #pragma unroll
        for (int i = 0; i < 8; i++) { S += ssum[i]; Q += ssq[i]; }
        float mean = S * (1.f / 2048.f);
        float var  = Q * (1.f / 2048.f) - mean * mean;
        float rstd = rsqrtf(var + 1e-5f);
        float sc = rstd * g1[c];
        float sh = be1[c] - mean * sc;
        g_stats[(s * 512 + c) * 2 + 0] = sc;
        g_stats[(s * 512 + c) * 2 + 1] = sh;
    }
}

// ---------------------------------------------------------------------------
// Host orchestration
// ---------------------------------------------------------------------------
extern "C" void kernel_launch(void* const* d_in, const int* in_sizes, int n_in,
                              void* d_out, int out_size) {
    const float* desc0 = (const float*)d_in[0];
    const float* desc1 = (const float*)d_in[1];
    const float* Wq  = (const float*)d_in[2];
    const float* bq  = (const float*)d_in[3];
    const float* Wk  = (const float*)d_in[4];
    const float* bk  = (const float*)d_in[5];
    const float* Wv  = (const float*)d_in[6];
    const float* bv  = (const float*)d_in[7];
    const float* Wm  = (const float*)d_in[8];
    const float* bm  = (const float*)d_in[9];
    const float* W1  = (const float*)d_in[10];
    const float* b1  = (const float*)d_in[11];
    const float* g1  = (const float*)d_in[12];
    const float* be1 = (const float*)d_in[13];
    const float* W2  = (const float*)d_in[14];
    const float* b2  = (const float*)d_in[15];
    float* out = (float*)d_out;

    float *qb, *kb, *vb, *msgb, *mmb, *hb, *statsb, *whi, *wlo;
    cudaGetSymbolAddress((void**)&qb,    g_q);
    cudaGetSymbolAddress((void**)&kb,    g_k);
    cudaGetSymbolAddress((void**)&vb,    g_v);
    cudaGetSymbolAddress((void**)&msgb,  g_msg);
    cudaGetSymbolAddress((void**)&mmb,   g_mm);
    cudaGetSymbolAddress((void**)&hb,    g_h);
    cudaGetSymbolAddress((void**)&statsb, g_stats);
    cudaGetSymbolAddress((void**)&whi,   g_whi);
    cudaGetSymbolAddress((void**)&wlo,   g_wlo);

    cudaFuncSetAttribute(attn_kernel,
                         cudaFuncAttributeMaxDynamicSharedMemorySize, ATTN_SMEM);

    presplit_kernel<<<(int)((TOTW / 4 + 255) / 256), 256>>>(Wq, Wk, Wv, Wm, W1, W2);

    cudaMemcpyAsync(out + 2 * (size_t)TEN, desc0, TEN * sizeof(float),
                    cudaMemcpyDeviceToDevice, 0);
    cudaMemcpyAsync(out + 3 * (size_t)TEN, desc1, TEN * sizeof(float),
                    cudaMemcpyDeviceToDevice, 0);

    const float* xa = desc0;
    const float* xb = desc1;

    for (int i = 0; i < 18; i++) {
        const float *sa, *sb, *ra, *rb;
        float *oa, *ob;
        if (i == 0) {
            sa = xa; sb = xb; ra = desc0; rb = desc1;
            oa = out;            ob = out + (size_t)TEN;
        } else if (i == 1) {
            sa = xb; sb = xa; ra = desc0; rb = desc1;
            oa = out + 4 * (size_t)TEN; ob = out + 5 * (size_t)TEN;
        } else {
            if ((i & 1) == 0) { sa = xa; sb = xb; }
            else              { sa = xb; sb = xa; }
            ra = xa; rb = xb;
            oa = out + (size_t)(2 + 2 * i) * TEN;
            ob = oa + (size_t)TEN;
        }

        const float* Wq_hi = whi + OFF_WQ + (size_t)i * 65536;
        const float* Wq_lo = wlo + OFF_WQ + (size_t)i * 65536;
        const float* Wk_hi = whi + OFF_WK + (size_t)i * 65536;
        const float* Wk_lo = wlo + OFF_WK + (size_t)i * 65536;
        const float* Wv_hi = whi + OFF_WV + (size_t)i * 65536;
        const float* Wv_lo = wlo + OFF_WV + (size_t)i * 65536;
        const float* Wm_hi = whi + OFF_WM + (size_t)i * 65536;
        const float* Wm_lo = wlo + OFF_WM + (size_t)i * 65536;
        const float* W1_hi = whi + OFF_W1 + (size_t)i * 262144;
        const float* W1_lo = wlo + OFF_W1 + (size_t)i * 262144;
        const float* W2_hi = whi + OFF_W2 + (size_t)i * 131072;
        const float* W2_lo = wlo + OFF_W2 + (size_t)i * 131072;
        const float* bq_i = bq + (size_t)i * 256;
        const float* bk_i = bk + (size_t)i * 256;
        const float* bv_i = bv + (size_t)i * 256;
        const float* bm_i = bm + (size_t)i * 256;
        const float* b1_i = b1 + (size_t)i * 512;
        const float* b2_i = b2 + (size_t)i * 256;
        const float* g1_i = g1 + (size_t)i * 512;
        const float* be_i = be1 + (size_t)i * 512;

        GArgs ga = {};
        ga.bnp[0] = statsb; ga.bnp[1] = statsb + 1024;

        // q/k/v merged
        ga.Whi[0] = Wq_hi; ga.Wlo[0] = Wq_lo; ga.bias[0] = bq_i;
        ga.Whi[1] = Wk_hi; ga.Wlo[1] = Wk_lo; ga.bias[1] = bk_i;
        ga.Whi[2] = Wv_hi; ga.Wlo[2] = Wv_lo; ga.bias[2] = bv_i;
        ga.X0[0][0] = xa; ga.X0[0][1] = xb;
        ga.X0[1][0] = sa; ga.X0[1][1] = sb;
        ga.X0[2][0] = sa; ga.X0[2][1] = sb;
        ga.out[0][0] = qb; ga.out[0][1] = qb + TEN;
        ga.out[1][0] = kb; ga.out[1][1] = kb + TEN;
        ga.out[2][0] = vb; ga.out[2][1] = vb + TEN;
        ga.X1[0] = ga.X1[1] = nullptr;
        ga.res[0] = ga.res[1] = nullptr;
        ga.M = 256; ga.K = 256; ga.K0 = 256; ga.use_bn = 0; ga.mtiles = 4;
        gemm_tc<<<dim3(32, 12, 2), 128>>>(ga);

        // attention
        attn_kernel<<<dim3(16, 8, 2), 256, ATTN_SMEM>>>();

        // msg projection
        ga.Whi[0] = Wm_hi; ga.Wlo[0] = Wm_lo; ga.bias[0] = bm_i;
        ga.X0[0][0] = msgb; ga.X0[0][1] = msgb + TEN;
        ga.out[0][0] = mmb; ga.out[0][1] = mmb + TEN;
        ga.M = 256; ga.K = 256; ga.K0 = 256; ga.use_bn = 0; ga.mtiles = 4;
        gemm_tc<<<dim3(32, 4, 2), 128>>>(ga);

        // h = W1 [x; msg] + b1
        ga.Whi[0] = W1_hi; ga.Wlo[0] = W1_lo; ga.bias[0] = b1_i;
        ga.X0[0][0] = xa; ga.X0[0][1] = xb;
        ga.X1[0] = mmb; ga.X1[1] = mmb + TEN;
        ga.out[0][0] = hb; ga.out[0][1] = hb + HTEN;
        ga.M = 512; ga.K = 512; ga.K0 = 256; ga.use_bn = 0; ga.mtiles = 8;
        gemm_tc<<<dim3(32, 8, 2), 128>>>(ga);

        // BN stats
        bn_stats_kernel<<<dim3(512, 2), 256>>>(g1_i, be_i);

        // out = res + W2 relu(BN(h)) + b2
        ga.Whi[0] = W2_hi; ga.Wlo[0] = W2_lo; ga.bias[0] = b2_i;
        ga.X0[0][0] = hb; ga.X0[0][1] = hb + HTEN;
        ga.X1[0] = ga.X1[1] = nullptr;
        ga.res[0] = ra; ga.res[1] = rb;
        ga.out[0][0] = oa; ga.out[0][1] = ob;
        ga.M = 256; ga.K = 512; ga.K0 = 512; ga.use_bn = 1; ga.mtiles = 4;
        gemm_tc<<<dim3(32, 4, 2), 128>>>(ga);
        ga.res[0] = ga.res[1] = nullptr;

        xa = oa; xb = ob;
    }
}

// round 7
// speedup vs baseline: 1.7321x; 1.1590x over previous
#include <cuda_runtime.h>
#include <math.h>

// ---------------------------------------------------------------------------
// AttentionalGNN: L=18 layers, D=256, H=4 (head dim 64), B=2, N=1024.
// Activations: [b2][C][N] fp32, channel c = d*4 + h.
// Round 7 (= round 6 resubmit after infra failure): GEMM gets 2-stage
// cp.async double buffering; B kept raw fp32 in smem with BN+relu and tf32
// hi/lo split done in registers at fragment load. Attention unchanged
// (tensor-core 3xTF32 + polynomial exp).
// ---------------------------------------------------------------------------

#define BB   2
#define DD   256
#define NN   1024
#define TEN  (BB*DD*NN)
#define HTEN (BB*512*NN)

// Scratch (device globals). [stream][b2][C][N]
__device__ float g_q  [2*TEN];
__device__ float g_k  [2*TEN];
__device__ float g_v  [2*TEN];
__device__ float g_msg[2*TEN];
__device__ float g_mm [2*TEN];
__device__ float g_h  [2*HTEN];
__device__ float g_stats[2*512*2];

// Pre-split weights (hi/lo), concatenated: Wq|Wk|Wv|Wm|W1|W2
#define SZ_D  (18L*256*256)
#define SZ_1  (18L*512*512)
#define SZ_2  (18L*256*512)
#define OFF_WQ 0L
#define OFF_WK (SZ_D)
#define OFF_WV (2*SZ_D)
#define OFF_WM (3*SZ_D)
#define OFF_W1 (4*SZ_D)
#define OFF_W2 (4*SZ_D + SZ_1)
#define TOTW   (4*SZ_D + SZ_1 + SZ_2)
__device__ float g_whi[TOTW];
__device__ float g_wlo[TOTW];

__device__ __forceinline__ float to_tf32(float x) {
    unsigned u;
    asm("cvt.rna.tf32.f32 %0, %1;" : "=r"(u) : "f"(x));
    return __uint_as_float(u);
}

#define MMA_TF32(acc, af, bf)                                                  \
    asm volatile(                                                              \
        "mma.sync.aligned.m16n8k8.row.col.f32.tf32.tf32.f32 "                  \
        "{%0,%1,%2,%3}, {%4,%5,%6,%7}, {%8,%9}, {%0,%1,%2,%3};"                \
        : "+f"(acc[0]), "+f"(acc[1]), "+f"(acc[2]), "+f"(acc[3])               \
        : "r"(af[0]), "r"(af[1]), "r"(af[2]), "r"(af[3]),                      \
          "r"(bf[0]), "r"(bf[1]))

__device__ __forceinline__ void cpa16(float* dst, const float* src) {
    unsigned sa = (unsigned)__cvta_generic_to_shared(dst);
    asm volatile("cp.async.ca.shared.global [%0], [%1], 16;" :: "r"(sa), "l"(src));
}

// exp on the FMA pipe: round-to-int trick + 2^f poly (deg 6), rel err ~2e-7.
__device__ __forceinline__ float expq(float x) {
    x = fmaxf(x, -80.f);
    float t = fmaf(x, 1.4426950408889634f, 12582912.f);
    float n = t - 12582912.f;
    float f = fmaf(x, 1.4426950408889634f, -n);
    float p = 0.0001540353039338161f;
    p = fmaf(p, f, 0.0013333558146428443f);
    p = fmaf(p, f, 0.009618129107628477f);
    p = fmaf(p, f, 0.05550410866482158f);
    p = fmaf(p, f, 0.2402265069591007f);
    p = fmaf(p, f, 0.6931471805599453f);
    p = fmaf(p, f, 1.0f);
    int ni = __float_as_int(t) - 0x4B400000;
    return __int_as_float(__float_as_int(p) + (ni << 23));
}

// ---------------------------------------------------------------------------
// Weight pre-split
// ---------------------------------------------------------------------------
__global__ __launch_bounds__(256) void presplit_kernel(
    const float* __restrict__ Wq, const float* __restrict__ Wk,
    const float* __restrict__ Wv, const float* __restrict__ Wm,
    const float* __restrict__ W1, const float* __restrict__ W2) {
    long i = ((long)blockIdx.x * 256 + threadIdx.x) * 4;
    if (i >= TOTW) return;
    const float* src; long off = i;
    if      (i < OFF_WK) { src = Wq; }
    else if (i < OFF_WV) { src = Wk; off = i - OFF_WK; }
    else if (i < OFF_WM) { src = Wv; off = i - OFF_WV; }
    else if (i < OFF_W1) { src = Wm; off = i - OFF_WM; }
    else if (i < OFF_W2) { src = W1; off = i - OFF_W1; }
    else                 { src = W2; off = i - OFF_W2; }
    float4 w = *(const float4*)(src + off);
    float4 h, l;
    h.x = to_tf32(w.x); l.x = w.x - h.x;
    h.y = to_tf32(w.y); l.y = w.y - h.y;
    h.z = to_tf32(w.z); l.z = w.z - h.z;
    h.w = to_tf32(w.w); l.w = w.w - h.w;
    *(float4*)(g_whi + i) = h;
    *(float4*)(g_wlo + i) = l;
}

// ---------------------------------------------------------------------------
// Tensor-core GEMM (3xTF32), 2-stage cp.async pipeline.
// Block tile 64x64x32, 128 threads (4 warps, 2Mx2N, warp tile 32x32).
// Dyn smem (floats): AH[2][64][36] | AL[2][64][36] | BS[2][32][68] | BN[2][64]
//                   = 4608 + 4608 + 4352 + 128 = 13696 floats = 54784 B.
// ---------------------------------------------------------------------------
struct GArgs {
    const float* Whi[3];
    const float* Wlo[3];
    const float* bias[3];
    const float* X0[3][2];
    const float* X1[2];
    const float* res[2];
    const float* bnp[2];
    float*       out[3][2];
    int M, K, K0, use_bn, mtiles;
};

#define GEMM_SMEM (13696 * 4)

__global__ __launch_bounds__(128) void gemm_tc(GArgs a) {
    extern __shared__ __align__(16) float smem[];
    // offsets (floats):  AH: 0 (2x2304) | AL: 4608 | BS: 9216 (2x2176) | BN: 13568 (2x64)

    const int s   = blockIdx.z;
    const int jt  = blockIdx.x;
    const int b2  = jt >> 4;
    const int n0  = (jt & 15) << 6;
    const int mat = blockIdx.y / a.mtiles;
    const int m0  = (blockIdx.y % a.mtiles) << 6;
    const int tid = threadIdx.x;
    const int warp = tid >> 5, lane = tid & 31;
    const int wm = (warp >> 1) << 5;
    const int wn = (warp & 1) << 5;
    const int g = lane >> 2, t = lane & 3;

    const int K = a.K, K0 = a.K0, M = a.M;
    const int use_bn = a.use_bn;
    const float* __restrict__ Whi = a.Whi[mat];
    const float* __restrict__ Wlo = a.Wlo[mat];
    const float* __restrict__ X0  = a.X0[mat][s];
    const float* __restrict__ X1  = a.X1[s];
    const float* __restrict__ bnp = a.bnp[s];

    float acc[2][4][4];
    #pragma unroll
    for (int mi = 0; mi < 2; mi++)
        #pragma unroll
        for (int ni = 0; ni < 4; ni++)
            #pragma unroll
            for (int r = 0; r < 4; r++) acc[mi][ni][r] = 0.f;

    auto load_tile = [&](int k0, int buf) {
        float* AHb = smem + buf * 2304;
        float* ALb = smem + 4608 + buf * 2304;
        float* BSb = smem + 9216 + buf * 2176;
        float* BNb = smem + 13568 + buf * 64;
        #pragma unroll
        for (int e = tid; e < 512; e += 128) {
            int m  = e >> 3;
            int kq = (e & 7) << 2;
            size_t woff = (size_t)(m0 + m) * K + k0 + kq;
            cpa16(AHb + m * 36 + kq, Whi + woff);
            cpa16(ALb + m * 36 + kq, Wlo + woff);
        }
        #pragma unroll
        for (int e = tid; e < 512; e += 128) {
            int kk = e >> 4;
            int nq = (e & 15) << 2;
            int k = k0 + kk;
            const float* src = (k < K0)
                ? X0 + ((size_t)b2 * K0 + k) * NN + n0 + nq
                : X1 + ((size_t)b2 * (K - K0) + (k - K0)) * NN + n0 + nq;
            cpa16(BSb + kk * 68 + nq, src);
        }
        if (use_bn && tid < 64) BNb[tid] = bnp[2 * k0 + tid];
        asm volatile("cp.async.commit_group;" ::: "memory");
    };

    const int niter = K >> 5;
    load_tile(0, 0);

    for (int it = 0; it < niter; it++) {
        const int buf = it & 1;
        if (it + 1 < niter) {
            load_tile((it + 1) << 5, buf ^ 1);
            asm volatile("cp.async.wait_group 1;" ::: "memory");
        } else {
            asm volatile("cp.async.wait_group 0;" ::: "memory");
        }
        __syncthreads();

        const float* AHb = smem + buf * 2304;
        const float* ALb = smem + 4608 + buf * 2304;
        const float* BSb = smem + 9216 + buf * 2176;
        const float* BNb = smem + 13568 + buf * 64;

        #pragma unroll
        for (int kk = 0; kk < 32; kk += 8) {
            unsigned afh[2][4], afl[2][4];
            #pragma unroll
            for (int mi = 0; mi < 2; mi++) {
                int r0 = wm + mi * 16 + g;
                afh[mi][0] = __float_as_uint(AHb[(r0    ) * 36 + kk + t    ]);
                afh[mi][1] = __float_as_uint(AHb[(r0 + 8) * 36 + kk + t    ]);
                afh[mi][2] = __float_as_uint(AHb[(r0    ) * 36 + kk + t + 4]);
                afh[mi][3] = __float_as_uint(AHb[(r0 + 8) * 36 + kk + t + 4]);
                afl[mi][0] = __float_as_uint(ALb[(r0    ) * 36 + kk + t    ]);
                afl[mi][1] = __float_as_uint(ALb[(r0 + 8) * 36 + kk + t    ]);
                afl[mi][2] = __float_as_uint(ALb[(r0    ) * 36 + kk + t + 4]);
                afl[mi][3] = __float_as_uint(ALb[(r0 + 8) * 36 + kk + t + 4]);
            }
            float sc0 = 1.f, sh0 = 0.f, sc1 = 1.f, sh1 = 0.f;
            if (use_bn) {
                sc0 = BNb[2 * (kk + t)];     sh0 = BNb[2 * (kk + t) + 1];
                sc1 = BNb[2 * (kk + t + 4)]; sh1 = BNb[2 * (kk + t + 4) + 1];
            }
            #pragma unroll
            for (int ni = 0; ni < 4; ni++) {
                int c = wn + ni * 8 + g;
                float b0 = BSb[(kk + t    ) * 68 + c];
                float b1 = BSb[(kk + t + 4) * 68 + c];
                if (use_bn) {
                    b0 = fmaxf(fmaf(b0, sc0, sh0), 0.f);
                    b1 = fmaxf(fmaf(b1, sc1, sh1), 0.f);
                }
                float h0 = to_tf32(b0), h1 = to_tf32(b1);
                unsigned bh2[2] = {__float_as_uint(h0), __float_as_uint(h1)};
                unsigned bl2[2] = {__float_as_uint(b0 - h0), __float_as_uint(b1 - h1)};
                #pragma unroll
                for (int mi = 0; mi < 2; mi++) {
                    MMA_TF32(acc[mi][ni], afh[mi], bl2);
                    MMA_TF32(acc[mi][ni], afl[mi], bh2);
                    MMA_TF32(acc[mi][ni], afh[mi], bh2);
                }
            }
        }
        __syncthreads();
    }

    const float* resp = a.res[s];
    const float* biasp = a.bias[mat];
    float* outp = a.out[mat][s];
    #pragma unroll
    for (int mi = 0; mi < 2; mi++) {
        #pragma unroll
        for (int half = 0; half < 2; half++) {
            int m = m0 + wm + mi * 16 + g + half * 8;
            float bb = biasp[m];
            #pragma unroll
            for (int ni = 0; ni < 4; ni++) {
                int col = n0 + wn + ni * 8 + 2 * t;
                size_t off = ((size_t)b2 * M + m) * NN + col;
                float2 c;
                c.x = acc[mi][ni][2 * half + 0] + bb;
                c.y = acc[mi][ni][2 * half + 1] + bb;
                if (resp) {
                    float2 r = *(const float2*)(resp + off);
                    c.x += r.x; c.y += r.y;
                }
                *(float2*)(outp + off) = c;
            }
        }
    }
}

// ---------------------------------------------------------------------------
// Tensor-core flash attention (3xTF32) — unchanged from round 5.
// ---------------------------------------------------------------------------
#define ATTN_SMEM (5 * 64 * 68 * 4)

__global__ __launch_bounds__(256) void attn_kernel() {
    extern __shared__ __align__(16) float sm[];
    float (*Qs)[68] = (float(*)[68])(sm);
    float (*Ks)[68] = (float(*)[68])(sm + 64 * 68);
    float (*Vs)[68] = (float(*)[68])(sm + 2 * 64 * 68);
    float (*Ph)[68] = (float(*)[68])(sm + 3 * 64 * 68);
    float (*Pl)[68] = (float(*)[68])(sm + 4 * 64 * 68);
    __shared__ float red_max[2][4][16];
    __shared__ float red_sum[2][4][16];

    const int qt = blockIdx.x;
    const int bh = blockIdx.y;
    const int s  = blockIdx.z;
    const int b2 = bh >> 2, h = bh & 3;
    const int q0 = qt << 6;
    const int tid = threadIdx.x;
    const int warp = tid >> 5, lane = tid & 31;
    const int g = lane >> 2, t = lane & 3;
    const int qw = warp >> 1, kw = warp & 1;
    const int qcol = qw << 4;
    const int kcol = kw << 5;

    size_t base = (size_t)s * TEN + (size_t)b2 * (DD * NN);
    const float* __restrict__ qp = g_q + base;
    const float* __restrict__ kp = g_k + base;
    const float* __restrict__ vp = g_v + base;
    float* mp = g_msg + base;

    for (int e = tid; e < 4096; e += 256) {
        int qi = e & 63, d = e >> 6;
        Qs[d][qi] = qp[(size_t)(d * 4 + h) * NN + q0 + qi] * 0.125f;
    }

    float oacc[4][4] = {};
    float mi2[2] = {-1e30f, -1e30f};
    float li2[2] = {0.f, 0.f};

    for (int kt = 0; kt < 16; kt++) {
        int m0k = kt << 6;
        __syncthreads();
        for (int e = tid; e < 4096; e += 256) {
            int kk = e & 63, d = e >> 6;
            size_t goff = (size_t)(d * 4 + h) * NN + m0k + kk;
            Ks[d][kk] = kp[goff];
            Vs[kk][d] = vp[goff];
        }
        __syncthreads();

        float sacc[4][4] = {};
        #pragma unroll
        for (int kk = 0; kk < 64; kk += 8) {
            float av[4];
            av[0] = Qs[kk + t    ][qcol + g    ];
            av[1] = Qs[kk + t    ][qcol + g + 8];
            av[2] = Qs[kk + t + 4][qcol + g    ];
            av[3] = Qs[kk + t + 4][qcol + g + 8];
            unsigned ah[4], al[4];
            #pragma unroll
            for (int j = 0; j < 4; j++) {
                float hi = to_tf32(av[j]);
                ah[j] = __float_as_uint(hi);
                al[j] = __float_as_uint(av[j] - hi);
            }
            #pragma unroll
            for (int ni = 0; ni < 4; ni++) {
                int c = kcol + ni * 8 + g;
                float b0 = Ks[kk + t    ][c];
                float b1 = Ks[kk + t + 4][c];
                float h0 = to_tf32(b0), h1 = to_tf32(b1);
                unsigned bh2[2] = {__float_as_uint(h0), __float_as_uint(h1)};
                unsigned bl2[2] = {__float_as_uint(b0 - h0), __float_as_uint(b1 - h1)};
                MMA_TF32(sacc[ni], ah, bl2);
                MMA_TF32(sacc[ni], al, bh2);
                MMA_TF32(sacc[ni], ah, bh2);
            }
        }

        float mloc[2] = {-1e30f, -1e30f};
        #pragma unroll
        for (int ni = 0; ni < 4; ni++) {
            mloc[0] = fmaxf(mloc[0], fmaxf(sacc[ni][0], sacc[ni][1]));
            mloc[1] = fmaxf(mloc[1], fmaxf(sacc[ni][2], sacc[ni][3]));
        }
        #pragma unroll
        for (int r = 0; r < 2; r++) {
            mloc[r] = fmaxf(mloc[r], __shfl_xor_sync(0xffffffffu, mloc[r], 1));
            mloc[r] = fmaxf(mloc[r], __shfl_xor_sync(0xffffffffu, mloc[r], 2));
        }
        if (t == 0) {
            red_max[kw][qw][g    ] = mloc[0];
            red_max[kw][qw][g + 8] = mloc[1];
        }
        __syncthreads();
        float mn[2], alpha[2];
        #pragma unroll
        for (int r = 0; r < 2; r++) {
            int row = g + r * 8;
            float mk = fmaxf(red_max[0][qw][row], red_max[1][qw][row]);
            mn[r] = fmaxf(mi2[r], mk);
            alpha[r] = expq(mi2[r] - mn[r]);
            mi2[r] = mn[r];
        }
        float rs[2] = {0.f, 0.f};
        #pragma unroll
        for (int ni = 0; ni < 4; ni++) {
            #pragma unroll
            for (int j = 0; j < 4; j++) {
                int r = j >> 1;
                float p = expq(sacc[ni][j] - mn[r]);
                sacc[ni][j] = p;
                rs[r] += p;
            }
        }
        #pragma unroll
        for (int r = 0; r < 2; r++) {
            rs[r] += __shfl_xor_sync(0xffffffffu, rs[r], 1);
            rs[r] += __shfl_xor_sync(0xffffffffu, rs[r], 2);
        }
        if (t == 0) {
            red_sum[kw][qw][g    ] = rs[0];
            red_sum[kw][qw][g + 8] = rs[1];
        }
        #pragma unroll
        for (int ni = 0; ni < 4; ni++) {
            #pragma unroll
            for (int r = 0; r < 2; r++) {
                int row = qcol + g + r * 8;
                int col = kcol + ni * 8 + 2 * t;
                float p0 = sacc[ni][2 * r], p1 = sacc[ni][2 * r + 1];
                float h0 = to_tf32(p0), h1 = to_tf32(p1);
                float2 ph = make_float2(h0, h1);
                float2 pl = make_float2(p0 - h0, p1 - h1);
                *(float2*)&Ph[row][col] = ph;
                *(float2*)&Pl[row][col] = pl;
            }
        }
        __syncthreads();
        #pragma unroll
        for (int r = 0; r < 2; r++) {
            int row = g + r * 8;
            float rstot = red_sum[0][qw][row] + red_sum[1][qw][row];
            li2[r] = li2[r] * alpha[r] + rstot;
        }
        #pragma unroll
        for (int ni = 0; ni < 4; ni++) {
            oacc[ni][0] *= alpha[0]; oacc[ni][1] *= alpha[0];
            oacc[ni][2] *= alpha[1]; oacc[ni][3] *= alpha[1];
        }

        #pragma unroll
        for (int kk = 0; kk < 64; kk += 8) {
            unsigned ah[4], al[4];
            ah[0] = __float_as_uint(Ph[qcol + g    ][kk + t    ]);
            ah[1] = __float_as_uint(Ph[qcol + g + 8][kk + t    ]);
            ah[2] = __float_as_uint(Ph[qcol + g    ][kk + t + 4]);
            ah[3] = __float_as_uint(Ph[qcol + g + 8][kk + t + 4]);
            al[0] = __float_as_uint(Pl[qcol + g    ][kk + t    ]);
            al[1] = __float_as_uint(Pl[qcol + g + 8][kk + t    ]);
            al[2] = __float_as_uint(Pl[qcol + g    ][kk + t + 4]);
            al[3] = __float_as_uint(Pl[qcol + g + 8][kk + t + 4]);
            #pragma unroll
            for (int ni = 0; ni < 4; ni++) {
                int c = kcol + ni * 8 + g;
                float b0 = Vs[kk + t    ][c];
                float b1 = Vs[kk + t + 4][c];
                float h0 = to_tf32(b0), h1 = to_tf32(b1);
                unsigned bh2[2] = {__float_as_uint(h0), __float_as_uint(h1)};
                unsigned bl2[2] = {__float_as_uint(b0 - h0), __float_as_uint(b1 - h1)};
                MMA_TF32(oacc[ni], ah, bl2);
                MMA_TF32(oacc[ni], al, bh2);
                MMA_TF32(oacc[ni], ah, bh2);
            }
        }
    }

    float inv[2] = {1.f / li2[0], 1.f / li2[1]};
    __syncthreads();
    #pragma unroll
    for (int ni = 0; ni < 4; ni++) {
        #pragma unroll
        for (int j = 0; j < 4; j++) {
            int r = j >> 1;
            int row_q = qcol + g + r * 8;
            int col_d = kcol + ni * 8 + 2 * t + (j & 1);
            Ph[col_d][row_q] = oacc[ni][j] * inv[r];
        }
    }
    __syncthreads();
    for (int e = tid; e < 4096; e += 256) {
        int qi = e & 63, d = e >> 6;
        mp[(size_t)(d * 4 + h) * NN + q0 + qi] = Ph[d][qi];
    }
}

// ---------------------------------------------------------------------------
// BatchNorm stats (unchanged).
// ---------------------------------------------------------------------------
__global__ __launch_bounds__(256) void bn_stats_kernel(const float* __restrict__ g1,
                                                       const float* __restrict__ be1) {
    const int c = blockIdx.x;
    const int s = blockIdx.y;
    const float* hp = g_h + (size_t)s * HTEN;
    int tid = threadIdx.x;
    float sum = 0.f, sq = 0.f;
    for (int idx = tid; idx < 2048; idx += 256) {
        int b2 = idx >> 10, n = idx & 1023;
        float v = hp[((size_t)b2 * 512 + c) * NN + n];
        sum += v;
        sq = fmaf(v, v, sq);
    }
    #pragma unroll
    for (int w = 16; w; w >>= 1) {
        sum += __shfl_xor_sync(0xffffffffu, sum, w);
        sq  += __shfl_xor_sync(0xffffffffu, sq,  w);
    }
    __shared__ float ssum[8], ssq[8];
    int wid = tid >> 5, lane = tid & 31;
    if (lane == 0) { ssum[wid] = sum; ssq[wid] = sq; }
    __syncthreads();
    if (tid == 0) {
        float S = 0.f, Q = 0.f;
        #pragma unroll
        for (int i = 0; i < 8; i++) { S += ssum[i]; Q += ssq[i]; }
        float mean = S * (1.f / 2048.f);
        float var  = Q * (1.f / 2048.f) - mean * mean;
        float rstd = rsqrtf(var + 1e-5f);
        float sc = rstd * g1[c];
        float sh = be1[c] - mean * sc;
        g_stats[(s * 512 + c) * 2 + 0] = sc;
        g_stats[(s * 512 + c) * 2 + 1] = sh;
    }
}

// ---------------------------------------------------------------------------
// Host orchestration
// ---------------------------------------------------------------------------
extern "C" void kernel_launch(void* const* d_in, const int* in_sizes, int n_in,
                              void* d_out, int out_size) {
    const float* desc0 = (const float*)d_in[0];
    const float* desc1 = (const float*)d_in[1];
    const float* Wq  = (const float*)d_in[2];
    const float* bq  = (const float*)d_in[3];
    const float* Wk  = (const float*)d_in[4];
    const float* bk  = (const float*)d_in[5];
    const float* Wv  = (const float*)d_in[6];
    const float* bv  = (const float*)d_in[7];
    const float* Wm  = (const float*)d_in[8];
    const float* bm  = (const float*)d_in[9];
    const float* W1  = (const float*)d_in[10];
    const float* b1  = (const float*)d_in[11];
    const float* g1  = (const float*)d_in[12];
    const float* be1 = (const float*)d_in[13];
    const float* W2  = (const float*)d_in[14];
    const float* b2  = (const float*)d_in[15];
    float* out = (float*)d_out;

    float *qb, *kb, *vb, *msgb, *mmb, *hb, *statsb, *whi, *wlo;
    cudaGetSymbolAddress((void**)&qb,    g_q);
    cudaGetSymbolAddress((void**)&kb,    g_k);
    cudaGetSymbolAddress((void**)&vb,    g_v);
    cudaGetSymbolAddress((void**)&msgb,  g_msg);
    cudaGetSymbolAddress((void**)&mmb,   g_mm);
    cudaGetSymbolAddress((void**)&hb,    g_h);
    cudaGetSymbolAddress((void**)&statsb, g_stats);
    cudaGetSymbolAddress((void**)&whi,   g_whi);
    cudaGetSymbolAddress((void**)&wlo,   g_wlo);

    cudaFuncSetAttribute(attn_kernel,
                         cudaFuncAttributeMaxDynamicSharedMemorySize, ATTN_SMEM);
    cudaFuncSetAttribute(gemm_tc,
                         cudaFuncAttributeMaxDynamicSharedMemorySize, GEMM_SMEM);

    presplit_kernel<<<(int)((TOTW / 4 + 255) / 256), 256>>>(Wq, Wk, Wv, Wm, W1, W2);

    cudaMemcpyAsync(out + 2 * (size_t)TEN, desc0, TEN * sizeof(float),
                    cudaMemcpyDeviceToDevice, 0);
    cudaMemcpyAsync(out + 3 * (size_t)TEN, desc1, TEN * sizeof(float),
                    cudaMemcpyDeviceToDevice, 0);

    const float* xa = desc0;
    const float* xb = desc1;

    for (int i = 0; i < 18; i++) {
        const float *sa, *sb, *ra, *rb;
        float *oa, *ob;
        if (i == 0) {
            sa = xa; sb = xb; ra = desc0; rb = desc1;
            oa = out;            ob = out + (size_t)TEN;
        } else if (i == 1) {
            sa = xb; sb = xa; ra = desc0; rb = desc1;
            oa = out + 4 * (size_t)TEN; ob = out + 5 * (size_t)TEN;
        } else {
            if ((i & 1) == 0) { sa = xa; sb = xb; }
            else              { sa = xb; sb = xa; }
            ra = xa; rb = xb;
            oa = out + (size_t)(2 + 2 * i) * TEN;
            ob = oa + (size_t)TEN;
        }

        const float* Wq_hi = whi + OFF_WQ + (size_t)i * 65536;
        const float* Wq_lo = wlo + OFF_WQ + (size_t)i * 65536;
        const float* Wk_hi = whi + OFF_WK + (size_t)i * 65536;
        const float* Wk_lo = wlo + OFF_WK + (size_t)i * 65536;
        const float* Wv_hi = whi + OFF_WV + (size_t)i * 65536;
        const float* Wv_lo = wlo + OFF_WV + (size_t)i * 65536;
        const float* Wm_hi = whi + OFF_WM + (size_t)i * 65536;
        const float* Wm_lo = wlo + OFF_WM + (size_t)i * 65536;
        const float* W1_hi = whi + OFF_W1 + (size_t)i * 262144;
        const float* W1_lo = wlo + OFF_W1 + (size_t)i * 262144;
        const float* W2_hi = whi + OFF_W2 + (size_t)i * 131072;
        const float* W2_lo = wlo + OFF_W2 + (size_t)i * 131072;
        const float* bq_i = bq + (size_t)i * 256;
        const float* bk_i = bk + (size_t)i * 256;
        const float* bv_i = bv + (size_t)i * 256;
        const float* bm_i = bm + (size_t)i * 256;
        const float* b1_i = b1 + (size_t)i * 512;
        const float* b2_i = b2 + (size_t)i * 256;
        const float* g1_i = g1 + (size_t)i * 512;
        const float* be_i = be1 + (size_t)i * 512;

        GArgs ga = {};
        ga.bnp[0] = statsb; ga.bnp[1] = statsb + 1024;

        // q/k/v merged
        ga.Whi[0] = Wq_hi; ga.Wlo[0] = Wq_lo; ga.bias[0] = bq_i;
        ga.Whi[1] = Wk_hi; ga.Wlo[1] = Wk_lo; ga.bias[1] = bk_i;
        ga.Whi[2] = Wv_hi; ga.Wlo[2] = Wv_lo; ga.bias[2] = bv_i;
        ga.X0[0][0] = xa; ga.X0[0][1] = xb;
        ga.X0[1][0] = sa; ga.X0[1][1] = sb;
        ga.X0[2][0] = sa; ga.X0[2][1] = sb;
        ga.out[0][0] = qb; ga.out[0][1] = qb + TEN;
        ga.out[1][0] = kb; ga.out[1][1] = kb + TEN;
        ga.out[2][0] = vb; ga.out[2][1] = vb + TEN;
        ga.X1[0] = ga.X1[1] = nullptr;
        ga.res[0] = ga.res[1] = nullptr;
        ga.M = 256; ga.K = 256; ga.K0 = 256; ga.use_bn = 0; ga.mtiles = 4;
        gemm_tc<<<dim3(32, 12, 2), 128, GEMM_SMEM>>>(ga);

        // attention
        attn_kernel<<<dim3(16, 8, 2), 256, ATTN_SMEM>>>();

        // msg projection
        ga.Whi[0] = Wm_hi; ga.Wlo[0] = Wm_lo; ga.bias[0] = bm_i;
        ga.X0[0][0] = msgb; ga.X0[0][1] = msgb + TEN;
        ga.out[0][0] = mmb; ga.out[0][1] = mmb + TEN;
        ga.M = 256; ga.K = 256; ga.K0 = 256; ga.use_bn = 0; ga.mtiles = 4;
        gemm_tc<<<dim3(32, 4, 2), 128, GEMM_SMEM>>>(ga);

        // h = W1 [x; msg] + b1
        ga.Whi[0] = W1_hi; ga.Wlo[0] = W1_lo; ga.bias[0] = b1_i;
        ga.X0[0][0] = xa; ga.X0[0][1] = xb;
        ga.X1[0] = mmb; ga.X1[1] = mmb + TEN;
        ga.out[0][0] = hb; ga.out[0][1] = hb + HTEN;
        ga.M = 512; ga.K = 512; ga.K0 = 256; ga.use_bn = 0; ga.mtiles = 8;
        gemm_tc<<<dim3(32, 8, 2), 128, GEMM_SMEM>>>(ga);

        // BN stats
        bn_stats_kernel<<<dim3(512, 2), 256>>>(g1_i, be_i);

        // out = res + W2 relu(BN(h)) + b2
        ga.Whi[0] = W2_hi; ga.Wlo[0] = W2_lo; ga.bias[0] = b2_i;
        ga.X0[0][0] = hb; ga.X0[0][1] = hb + HTEN;
        ga.X1[0] = ga.X1[1] = nullptr;
        ga.res[0] = ra; ga.res[1] = rb;
        ga.out[0][0] = oa; ga.out[0][1] = ob;
        ga.M = 256; ga.K = 512; ga.K0 = 512; ga.use_bn = 1; ga.mtiles = 4;
        gemm_tc<<<dim3(32, 4, 2), 128, GEMM_SMEM>>>(ga);
        ga.res[0] = ga.res[1] = nullptr;

        xa = oa; xb = ob;
    }
}

// round 10
// speedup vs baseline: 1.8184x; 1.0499x over previous
#include <cuda_runtime.h>
#include <math.h>

// ---------------------------------------------------------------------------
// AttentionalGNN: L=18 layers, D=256, H=4 (head dim 64), B=2, N=1024.
// Activations: [b2][C][N] fp32, channel c = d*4 + h.
// Round 10 (= round 8 source, third attempt after broker failures):
// attention data-path cleanup — Q pre-split once (Qh/Ql smem), raw-P single
// buffer (split at PV fragment load), V kept [d][k] (no smem transpose,
// cp.async 16B for K and V). GEMM unchanged from round 7.
// ---------------------------------------------------------------------------

#define BB   2
#define DD   256
#define NN   1024
#define TEN  (BB*DD*NN)
#define HTEN (BB*512*NN)

// Scratch (device globals). [stream][b2][C][N]
__device__ float g_q  [2*TEN];
__device__ float g_k  [2*TEN];
__device__ float g_v  [2*TEN];
__device__ float g_msg[2*TEN];
__device__ float g_mm [2*TEN];
__device__ float g_h  [2*HTEN];
__device__ float g_stats[2*512*2];

// Pre-split weights (hi/lo), concatenated: Wq|Wk|Wv|Wm|W1|W2
#define SZ_D  (18L*256*256)
#define SZ_1  (18L*512*512)
#define SZ_2  (18L*256*512)
#define OFF_WQ 0L
#define OFF_WK (SZ_D)
#define OFF_WV (2*SZ_D)
#define OFF_WM (3*SZ_D)
#define OFF_W1 (4*SZ_D)
#define OFF_W2 (4*SZ_D + SZ_1)
#define TOTW   (4*SZ_D + SZ_1 + SZ_2)
__device__ float g_whi[TOTW];
__device__ float g_wlo[TOTW];

__device__ __forceinline__ float to_tf32(float x) {
    unsigned u;
    asm("cvt.rna.tf32.f32 %0, %1;" : "=r"(u) : "f"(x));
    return __uint_as_float(u);
}

#define MMA_TF32(acc, af, bf)                                                  \
    asm volatile(                                                              \
        "mma.sync.aligned.m16n8k8.row.col.f32.tf32.tf32.f32 "                  \
        "{%0,%1,%2,%3}, {%4,%5,%6,%7}, {%8,%9}, {%0,%1,%2,%3};"                \
        : "+f"(acc[0]), "+f"(acc[1]), "+f"(acc[2]), "+f"(acc[3])               \
        : "r"(af[0]), "r"(af[1]), "r"(af[2]), "r"(af[3]),                      \
          "r"(bf[0]), "r"(bf[1]))

__device__ __forceinline__ void cpa16(float* dst, const float* src) {
    unsigned sa = (unsigned)__cvta_generic_to_shared(dst);
    asm volatile("cp.async.ca.shared.global [%0], [%1], 16;" :: "r"(sa), "l"(src));
}

// exp on the FMA pipe: round-to-int trick + 2^f poly (deg 6), rel err ~2e-7.
__device__ __forceinline__ float expq(float x) {
    x = fmaxf(x, -80.f);
    float t = fmaf(x, 1.4426950408889634f, 12582912.f);
    float n = t - 12582912.f;
    float f = fmaf(x, 1.4426950408889634f, -n);
    float p = 0.0001540353039338161f;
    p = fmaf(p, f, 0.0013333558146428443f);
    p = fmaf(p, f, 0.009618129107628477f);
    p = fmaf(p, f, 0.05550410866482158f);
    p = fmaf(p, f, 0.2402265069591007f);
    p = fmaf(p, f, 0.6931471805599453f);
    p = fmaf(p, f, 1.0f);
    int ni = __float_as_int(t) - 0x4B400000;
    return __int_as_float(__float_as_int(p) + (ni << 23));
}

// ---------------------------------------------------------------------------
// Weight pre-split
// ---------------------------------------------------------------------------
__global__ __launch_bounds__(256) void presplit_kernel(
    const float* __restrict__ Wq, const float* __restrict__ Wk,
    const float* __restrict__ Wv, const float* __restrict__ Wm,
    const float* __restrict__ W1, const float* __restrict__ W2) {
    long i = ((long)blockIdx.x * 256 + threadIdx.x) * 4;
    if (i >= TOTW) return;
    const float* src; long off = i;
    if      (i < OFF_WK) { src = Wq; }
    else if (i < OFF_WV) { src = Wk; off = i - OFF_WK; }
    else if (i < OFF_WM) { src = Wv; off = i - OFF_WV; }
    else if (i < OFF_W1) { src = Wm; off = i - OFF_WM; }
    else if (i < OFF_W2) { src = W1; off = i - OFF_W1; }
    else                 { src = W2; off = i - OFF_W2; }
    float4 w = *(const float4*)(src + off);
    float4 h, l;
    h.x = to_tf32(w.x); l.x = w.x - h.x;
    h.y = to_tf32(w.y); l.y = w.y - h.y;
    h.z = to_tf32(w.z); l.z = w.z - h.z;
    h.w = to_tf32(w.w); l.w = w.w - h.w;
    *(float4*)(g_whi + i) = h;
    *(float4*)(g_wlo + i) = l;
}

// ---------------------------------------------------------------------------
// Tensor-core GEMM (3xTF32), 2-stage cp.async pipeline (unchanged).
// ---------------------------------------------------------------------------
struct GArgs {
    const float* Whi[3];
    const float* Wlo[3];
    const float* bias[3];
    const float* X0[3][2];
    const float* X1[2];
    const float* res[2];
    const float* bnp[2];
    float*       out[3][2];
    int M, K, K0, use_bn, mtiles;
};

#define GEMM_SMEM (13696 * 4)

__global__ __launch_bounds__(128) void gemm_tc(GArgs a) {
    extern __shared__ __align__(16) float smem[];
    // offsets (floats):  AH: 0 (2x2304) | AL: 4608 | BS: 9216 (2x2176) | BN: 13568 (2x64)

    const int s   = blockIdx.z;
    const int jt  = blockIdx.x;
    const int b2  = jt >> 4;
    const int n0  = (jt & 15) << 6;
    const int mat = blockIdx.y / a.mtiles;
    const int m0  = (blockIdx.y % a.mtiles) << 6;
    const int tid = threadIdx.x;
    const int warp = tid >> 5, lane = tid & 31;
    const int wm = (warp >> 1) << 5;
    const int wn = (warp & 1) << 5;
    const int g = lane >> 2, t = lane & 3;

    const int K = a.K, K0 = a.K0, M = a.M;
    const int use_bn = a.use_bn;
    const float* __restrict__ Whi = a.Whi[mat];
    const float* __restrict__ Wlo = a.Wlo[mat];
    const float* __restrict__ X0  = a.X0[mat][s];
    const float* __restrict__ X1  = a.X1[s];
    const float* __restrict__ bnp = a.bnp[s];

    float acc[2][4][4];
    #pragma unroll
    for (int mi = 0; mi < 2; mi++)
        #pragma unroll
        for (int ni = 0; ni < 4; ni++)
            #pragma unroll
            for (int r = 0; r < 4; r++) acc[mi][ni][r] = 0.f;

    auto load_tile = [&](int k0, int buf) {
        float* AHb = smem + buf * 2304;
        float* ALb = smem + 4608 + buf * 2304;
        float* BSb = smem + 9216 + buf * 2176;
        float* BNb = smem + 13568 + buf * 64;
        #pragma unroll
        for (int e = tid; e < 512; e += 128) {
            int m  = e >> 3;
            int kq = (e & 7) << 2;
            size_t woff = (size_t)(m0 + m) * K + k0 + kq;
            cpa16(AHb + m * 36 + kq, Whi + woff);
            cpa16(ALb + m * 36 + kq, Wlo + woff);
        }
        #pragma unroll
        for (int e = tid; e < 512; e += 128) {
            int kk = e >> 4;
            int nq = (e & 15) << 2;
            int k = k0 + kk;
            const float* src = (k < K0)
                ? X0 + ((size_t)b2 * K0 + k) * NN + n0 + nq
                : X1 + ((size_t)b2 * (K - K0) + (k - K0)) * NN + n0 + nq;
            cpa16(BSb + kk * 68 + nq, src);
        }
        if (use_bn && tid < 64) BNb[tid] = bnp[2 * k0 + tid];
        asm volatile("cp.async.commit_group;" ::: "memory");
    };

    const int niter = K >> 5;
    load_tile(0, 0);

    for (int it = 0; it < niter; it++) {
        const int buf = it & 1;
        if (it + 1 < niter) {
            load_tile((it + 1) << 5, buf ^ 1);
            asm volatile("cp.async.wait_group 1;" ::: "memory");
        } else {
            asm volatile("cp.async.wait_group 0;" ::: "memory");
        }
        __syncthreads();

        const float* AHb = smem + buf * 2304;
        const float* ALb = smem + 4608 + buf * 2304;
        const float* BSb = smem + 9216 + buf * 2176;
        const float* BNb = smem + 13568 + buf * 64;

        #pragma unroll
        for (int kk = 0; kk < 32; kk += 8) {
            unsigned afh[2][4], afl[2][4];
            #pragma unroll
            for (int mi = 0; mi < 2; mi++) {
                int r0 = wm + mi * 16 + g;
                afh[mi][0] = __float_as_uint(AHb[(r0    ) * 36 + kk + t    ]);
                afh[mi][1] = __float_as_uint(AHb[(r0 + 8) * 36 + kk + t    ]);
                afh[mi][2] = __float_as_uint(AHb[(r0    ) * 36 + kk + t + 4]);
                afh[mi][3] = __float_as_uint(AHb[(r0 + 8) * 36 + kk + t + 4]);
                afl[mi][0] = __float_as_uint(ALb[(r0    ) * 36 + kk + t    ]);
                afl[mi][1] = __float_as_uint(ALb[(r0 + 8) * 36 + kk + t    ]);
                afl[mi][2] = __float_as_uint(ALb[(r0    ) * 36 + kk + t + 4]);
                afl[mi][3] = __float_as_uint(ALb[(r0 + 8) * 36 + kk + t + 4]);
            }
            float sc0 = 1.f, sh0 = 0.f, sc1 = 1.f, sh1 = 0.f;
            if (use_bn) {
                sc0 = BNb[2 * (kk + t)];     sh0 = BNb[2 * (kk + t) + 1];
                sc1 = BNb[2 * (kk + t + 4)]; sh1 = BNb[2 * (kk + t + 4) + 1];
            }
            #pragma unroll
            for (int ni = 0; ni < 4; ni++) {
                int c = wn + ni * 8 + g;
                float b0 = BSb[(kk + t    ) * 68 + c];
                float b1 = BSb[(kk + t + 4) * 68 + c];
                if (use_bn) {
                    b0 = fmaxf(fmaf(b0, sc0, sh0), 0.f);
                    b1 = fmaxf(fmaf(b1, sc1, sh1), 0.f);
                }
                float h0 = to_tf32(b0), h1 = to_tf32(b1);
                unsigned bh2[2] = {__float_as_uint(h0), __float_as_uint(h1)};
                unsigned bl2[2] = {__float_as_uint(b0 - h0), __float_as_uint(b1 - h1)};
                #pragma unroll
                for (int mi = 0; mi < 2; mi++) {
                    MMA_TF32(acc[mi][ni], afh[mi], bl2);
                    MMA_TF32(acc[mi][ni], afl[mi], bh2);
                    MMA_TF32(acc[mi][ni], afh[mi], bh2);
                }
            }
        }
        __syncthreads();
    }

    const float* resp = a.res[s];
    const float* biasp = a.bias[mat];
    float* outp = a.out[mat][s];
    #pragma unroll
    for (int mi = 0; mi < 2; mi++) {
        #pragma unroll
        for (int half = 0; half < 2; half++) {
            int m = m0 + wm + mi * 16 + g + half * 8;
            float bb = biasp[m];
            #pragma unroll
            for (int ni = 0; ni < 4; ni++) {
                int col = n0 + wn + ni * 8 + 2 * t;
                size_t off = ((size_t)b2 * M + m) * NN + col;
                float2 c;
                c.x = acc[mi][ni][2 * half + 0] + bb;
                c.y = acc[mi][ni][2 * half + 1] + bb;
                if (resp) {
                    float2 r = *(const float2*)(resp + off);
                    c.x += r.x; c.y += r.y;
                }
                *(float2*)(outp + off) = c;
            }
        }
    }
}

// ---------------------------------------------------------------------------
// Tensor-core flash attention (3xTF32):
//  - Qh/Ql pre-split once into smem
//  - P stored raw (single buffer), hi/lo split at PV fragment load
//  - V kept in [d][k] layout (same as K): no smem transpose, cp.async 16B
// Buffers (stride 68): Qh | Ql | Ks[d][k] | Vs[d][k] | Ps[q][k] = 87040 B.
// ---------------------------------------------------------------------------
#define ATTN_SMEM (5 * 64 * 68 * 4)

__global__ __launch_bounds__(256) void attn_kernel() {
    extern __shared__ __align__(16) float sm[];
    float (*Qh)[68] = (float(*)[68])(sm);              // [d][q] hi (scaled)
    float (*Ql)[68] = (float(*)[68])(sm + 4352);       // [d][q] lo
    float (*Ks)[68] = (float(*)[68])(sm + 2 * 4352);   // [d][k]
    float (*Vs)[68] = (float(*)[68])(sm + 3 * 4352);   // [d][k]
    float (*Ps)[68] = (float(*)[68])(sm + 4 * 4352);   // [q][k] raw P; then [d][q] out
    __shared__ float red_max[2][4][16];
    __shared__ float red_sum[2][4][16];

    const int qt = blockIdx.x;
    const int bh = blockIdx.y;
    const int s  = blockIdx.z;
    const int b2 = bh >> 2, h = bh & 3;
    const int q0 = qt << 6;
    const int tid = threadIdx.x;
    const int warp = tid >> 5, lane = tid & 31;
    const int g = lane >> 2, t = lane & 3;
    const int qw = warp >> 1, kw = warp & 1;
    const int qcol = qw << 4;        // warp q base
    const int kcol = kw << 5;        // warp k base (S) == warp d base (PV)

    size_t base = (size_t)s * TEN + (size_t)b2 * (DD * NN);
    const float* __restrict__ qp = g_q + base;
    const float* __restrict__ kp = g_k + base;
    const float* __restrict__ vp = g_v + base;
    float* mp = g_msg + base;

    // load Q tile [d][q], fold 1/8 scale, split once
    for (int e = tid; e < 4096; e += 256) {
        int qi = e & 63, d = e >> 6;
        float v = qp[(size_t)(d * 4 + h) * NN + q0 + qi] * 0.125f;
        float hi = to_tf32(v);
        Qh[d][qi] = hi;
        Ql[d][qi] = v - hi;
    }

    float oacc[4][4] = {};
    float mi2[2] = {-1e30f, -1e30f};
    float li2[2] = {0.f, 0.f};

    for (int kt = 0; kt < 16; kt++) {
        int m0k = kt << 6;
        __syncthreads();   // prev iter done reading Ks/Vs/Ps
        // cp.async K and V tiles (identical [d][k] layout, 16B chunks)
        for (int e = tid; e < 1024; e += 256) {
            int d  = e >> 4;
            int c4 = (e & 15) << 2;
            size_t goff = (size_t)(d * 4 + h) * NN + m0k + c4;
            cpa16(&Ks[d][c4], kp + goff);
            cpa16(&Vs[d][c4], vp + goff);
        }
        asm volatile("cp.async.commit_group;\n\tcp.async.wait_group 0;" ::: "memory");
        __syncthreads();

        // ----- S = Q^T K (3xTF32), warp tile 16q x 32k -----
        float sacc[4][4] = {};
        #pragma unroll
        for (int kk = 0; kk < 64; kk += 8) {
            unsigned ah[4], al[4];
            ah[0] = __float_as_uint(Qh[kk + t    ][qcol + g    ]);
            ah[1] = __float_as_uint(Qh[kk + t    ][qcol + g + 8]);
            ah[2] = __float_as_uint(Qh[kk + t + 4][qcol + g    ]);
            ah[3] = __float_as_uint(Qh[kk + t + 4][qcol + g + 8]);
            al[0] = __float_as_uint(Ql[kk + t    ][qcol + g    ]);
            al[1] = __float_as_uint(Ql[kk + t    ][qcol + g + 8]);
            al[2] = __float_as_uint(Ql[kk + t + 4][qcol + g    ]);
            al[3] = __float_as_uint(Ql[kk + t + 4][qcol + g + 8]);
            #pragma unroll
            for (int ni = 0; ni < 4; ni++) {
                int c = kcol + ni * 8 + g;
                float b0 = Ks[kk + t    ][c];
                float b1 = Ks[kk + t + 4][c];
                float h0 = to_tf32(b0), h1 = to_tf32(b1);
                unsigned bh2[2] = {__float_as_uint(h0), __float_as_uint(h1)};
                unsigned bl2[2] = {__float_as_uint(b0 - h0), __float_as_uint(b1 - h1)};
                MMA_TF32(sacc[ni], ah, bl2);
                MMA_TF32(sacc[ni], al, bh2);
                MMA_TF32(sacc[ni], ah, bh2);
            }
        }

        // ----- online softmax -----
        float mloc[2] = {-1e30f, -1e30f};
        #pragma unroll
        for (int ni = 0; ni < 4; ni++) {
            mloc[0] = fmaxf(mloc[0], fmaxf(sacc[ni][0], sacc[ni][1]));
            mloc[1] = fmaxf(mloc[1], fmaxf(sacc[ni][2], sacc[ni][3]));
        }
        #pragma unroll
        for (int r = 0; r < 2; r++) {
            mloc[r] = fmaxf(mloc[r], __shfl_xor_sync(0xffffffffu, mloc[r], 1));
            mloc[r] = fmaxf(mloc[r], __shfl_xor_sync(0xffffffffu, mloc[r], 2));
        }
        if (t == 0) {
            red_max[kw][qw][g    ] = mloc[0];
            red_max[kw][qw][g + 8] = mloc[1];
        }
        __syncthreads();
        float mn[2], alpha[2];
        #pragma unroll
        for (int r = 0; r < 2; r++) {
            int row = g + r * 8;
            float mk = fmaxf(red_max[0][qw][row], red_max[1][qw][row]);
            mn[r] = fmaxf(mi2[r], mk);
            alpha[r] = expq(mi2[r] - mn[r]);
            mi2[r] = mn[r];
        }
        float rs[2] = {0.f, 0.f};
        #pragma unroll
        for (int ni = 0; ni < 4; ni++) {
            #pragma unroll
            for (int j = 0; j < 4; j++) {
                int r = j >> 1;
                float p = expq(sacc[ni][j] - mn[r]);
                sacc[ni][j] = p;
                rs[r] += p;
            }
        }
        #pragma unroll
        for (int r = 0; r < 2; r++) {
            rs[r] += __shfl_xor_sync(0xffffffffu, rs[r], 1);
            rs[r] += __shfl_xor_sync(0xffffffffu, rs[r], 2);
        }
        if (t == 0) {
            red_sum[kw][qw][g    ] = rs[0];
            red_sum[kw][qw][g + 8] = rs[1];
        }
        // stage raw P [q][k]
        #pragma unroll
        for (int ni = 0; ni < 4; ni++) {
            #pragma unroll
            for (int r = 0; r < 2; r++) {
                int row = qcol + g + r * 8;
                int col = kcol + ni * 8 + 2 * t;
                *(float2*)&Ps[row][col] = make_float2(sacc[ni][2 * r], sacc[ni][2 * r + 1]);
            }
        }
        __syncthreads();
        #pragma unroll
        for (int r = 0; r < 2; r++) {
            int row = g + r * 8;
            float rstot = red_sum[0][qw][row] + red_sum[1][qw][row];
            li2[r] = li2[r] * alpha[r] + rstot;
        }
        // rescale O
        #pragma unroll
        for (int ni = 0; ni < 4; ni++) {
            oacc[ni][0] *= alpha[0]; oacc[ni][1] *= alpha[0];
            oacc[ni][2] *= alpha[1]; oacc[ni][3] *= alpha[1];
        }

        // ----- O += P V (3xTF32), warp tile 16q x 32d, full 64 k -----
        // B operand from Vs[d][k]: B[k][n=d] = Vs[n][k]
        #pragma unroll
        for (int kk = 0; kk < 64; kk += 8) {
            float a0 = Ps[qcol + g    ][kk + t    ];
            float a1 = Ps[qcol + g + 8][kk + t    ];
            float a2 = Ps[qcol + g    ][kk + t + 4];
            float a3 = Ps[qcol + g + 8][kk + t + 4];
            float ah0 = to_tf32(a0), ah1 = to_tf32(a1);
            float ah2 = to_tf32(a2), ah3 = to_tf32(a3);
            unsigned ah[4] = {__float_as_uint(ah0), __float_as_uint(ah1),
                              __float_as_uint(ah2), __float_as_uint(ah3)};
            unsigned al[4] = {__float_as_uint(a0 - ah0), __float_as_uint(a1 - ah1),
                              __float_as_uint(a2 - ah2), __float_as_uint(a3 - ah3)};
            #pragma unroll
            for (int ni = 0; ni < 4; ni++) {
                int c = kcol + ni * 8 + g;   // d column
                float b0 = Vs[c][kk + t    ];
                float b1 = Vs[c][kk + t + 4];
                float h0 = to_tf32(b0), h1 = to_tf32(b1);
                unsigned bh2[2] = {__float_as_uint(h0), __float_as_uint(h1)};
                unsigned bl2[2] = {__float_as_uint(b0 - h0), __float_as_uint(b1 - h1)};
                MMA_TF32(oacc[ni], ah, bl2);
                MMA_TF32(oacc[ni], al, bh2);
                MMA_TF32(oacc[ni], ah, bh2);
            }
        }
    }

    float inv[2] = {1.f / li2[0], 1.f / li2[1]};
    __syncthreads();   // all PV reads of Ps done; reuse as [d][q] staging
    #pragma unroll
    for (int ni = 0; ni < 4; ni++) {
        #pragma unroll
        for (int j = 0; j < 4; j++) {
            int r = j >> 1;
            int row_q = qcol + g + r * 8;
            int col_d = kcol + ni * 8 + 2 * t + (j & 1);
            Ps[col_d][row_q] = oacc[ni][j] * inv[r];
        }
    }
    __syncthreads();
    for (int e = tid; e < 4096; e += 256) {
        int qi = e & 63, d = e >> 6;
        mp[(size_t)(d * 4 + h) * NN + q0 + qi] = Ps[d][qi];
    }
}

// ---------------------------------------------------------------------------
// BatchNorm stats (unchanged).
// ---------------------------------------------------------------------------
__global__ __launch_bounds__(256) void bn_stats_kernel(const float* __restrict__ g1,
                                                       const float* __restrict__ be1) {
    const int c = blockIdx.x;
    const int s = blockIdx.y;
    const float* hp = g_h + (size_t)s * HTEN;
    int tid = threadIdx.x;
    float sum = 0.f, sq = 0.f;
    for (int idx = tid; idx < 2048; idx += 256) {
        int b2 = idx >> 10, n = idx & 1023;
        float v = hp[((size_t)b2 * 512 + c) * NN + n];
        sum += v;
        sq = fmaf(v, v, sq);
    }
    #pragma unroll
    for (int w = 16; w; w >>= 1) {
        sum += __shfl_xor_sync(0xffffffffu, sum, w);
        sq  += __shfl_xor_sync(0xffffffffu, sq,  w);
    }
    __shared__ float ssum[8], ssq[8];
    int wid = tid >> 5, lane = tid & 31;
    if (lane == 0) { ssum[wid] = sum; ssq[wid] = sq; }
    __syncthreads();
    if (tid == 0) {
        float S = 0.f, Q = 0.f;
        #pragma unroll
        for (int i = 0; i < 8; i++) { S += ssum[i]; Q += ssq[i]; }
        float mean = S * (1.f / 2048.f);
        float var  = Q * (1.f / 2048.f) - mean * mean;
        float rstd = rsqrtf(var + 1e-5f);
        float sc = rstd * g1[c];
        float sh = be1[c] - mean * sc;
        g_stats[(s * 512 + c) * 2 + 0] = sc;
        g_stats[(s * 512 + c) * 2 + 1] = sh;
    }
}

// ---------------------------------------------------------------------------
// Host orchestration
// ---------------------------------------------------------------------------
extern "C" void kernel_launch(void* const* d_in, const int* in_sizes, int n_in,
                              void* d_out, int out_size) {
    const float* desc0 = (const float*)d_in[0];
    const float* desc1 = (const float*)d_in[1];
    const float* Wq  = (const float*)d_in[2];
    const float* bq  = (const float*)d_in[3];
    const float* Wk  = (const float*)d_in[4];
    const float* bk  = (const float*)d_in[5];
    const float* Wv  = (const float*)d_in[6];
    const float* bv  = (const float*)d_in[7];
    const float* Wm  = (const float*)d_in[8];
    const float* bm  = (const float*)d_in[9];
    const float* W1  = (const float*)d_in[10];
    const float* b1  = (const float*)d_in[11];
    const float* g1  = (const float*)d_in[12];
    const float* be1 = (const float*)d_in[13];
    const float* W2  = (const float*)d_in[14];
    const float* b2  = (const float*)d_in[15];
    float* out = (float*)d_out;

    float *qb, *kb, *vb, *msgb, *mmb, *hb, *statsb, *whi, *wlo;
    cudaGetSymbolAddress((void**)&qb,    g_q);
    cudaGetSymbolAddress((void**)&kb,    g_k);
    cudaGetSymbolAddress((void**)&vb,    g_v);
    cudaGetSymbolAddress((void**)&msgb,  g_msg);
    cudaGetSymbolAddress((void**)&mmb,   g_mm);
    cudaGetSymbolAddress((void**)&hb,    g_h);
    cudaGetSymbolAddress((void**)&statsb, g_stats);
    cudaGetSymbolAddress((void**)&whi,   g_whi);
    cudaGetSymbolAddress((void**)&wlo,   g_wlo);

    cudaFuncSetAttribute(attn_kernel,
                         cudaFuncAttributeMaxDynamicSharedMemorySize, ATTN_SMEM);
    cudaFuncSetAttribute(gemm_tc,
                         cudaFuncAttributeMaxDynamicSharedMemorySize, GEMM_SMEM);

    presplit_kernel<<<(int)((TOTW / 4 + 255) / 256), 256>>>(Wq, Wk, Wv, Wm, W1, W2);

    cudaMemcpyAsync(out + 2 * (size_t)TEN, desc0, TEN * sizeof(float),
                    cudaMemcpyDeviceToDevice, 0);
    cudaMemcpyAsync(out + 3 * (size_t)TEN, desc1, TEN * sizeof(float),
                    cudaMemcpyDeviceToDevice, 0);

    const float* xa = desc0;
    const float* xb = desc1;

    for (int i = 0; i < 18; i++) {
        const float *sa, *sb, *ra, *rb;
        float *oa, *ob;
        if (i == 0) {
            sa = xa; sb = xb; ra = desc0; rb = desc1;
            oa = out;            ob = out + (size_t)TEN;
        } else if (i == 1) {
            sa = xb; sb = xa; ra = desc0; rb = desc1;
            oa = out + 4 * (size_t)TEN; ob = out + 5 * (size_t)TEN;
        } else {
            if ((i & 1) == 0) { sa = xa; sb = xb; }
            else              { sa = xb; sb = xa; }
            ra = xa; rb = xb;
            oa = out + (size_t)(2 + 2 * i) * TEN;
            ob = oa + (size_t)TEN;
        }

        const float* Wq_hi = whi + OFF_WQ + (size_t)i * 65536;
        const float* Wq_lo = wlo + OFF_WQ + (size_t)i * 65536;
        const float* Wk_hi = whi + OFF_WK + (size_t)i * 65536;
        const float* Wk_lo = wlo + OFF_WK + (size_t)i * 65536;
        const float* Wv_hi = whi + OFF_WV + (size_t)i * 65536;
        const float* Wv_lo = wlo + OFF_WV + (size_t)i * 65536;
        const float* Wm_hi = whi + OFF_WM + (size_t)i * 65536;
        const float* Wm_lo = wlo + OFF_WM + (size_t)i * 65536;
        const float* W1_hi = whi + OFF_W1 + (size_t)i * 262144;
        const float* W1_lo = wlo + OFF_W1 + (size_t)i * 262144;
        const float* W2_hi = whi + OFF_W2 + (size_t)i * 131072;
        const float* W2_lo = wlo + OFF_W2 + (size_t)i * 131072;
        const float* bq_i = bq + (size_t)i * 256;
        const float* bk_i = bk + (size_t)i * 256;
        const float* bv_i = bv + (size_t)i * 256;
        const float* bm_i = bm + (size_t)i * 256;
        const float* b1_i = b1 + (size_t)i * 512;
        const float* b2_i = b2 + (size_t)i * 256;
        const float* g1_i = g1 + (size_t)i * 512;
        const float* be_i = be1 + (size_t)i * 512;

        GArgs ga = {};
        ga.bnp[0] = statsb; ga.bnp[1] = statsb + 1024;

        // q/k/v merged
        ga.Whi[0] = Wq_hi; ga.Wlo[0] = Wq_lo; ga.bias[0] = bq_i;
        ga.Whi[1] = Wk_hi; ga.Wlo[1] = Wk_lo; ga.bias[1] = bk_i;
        ga.Whi[2] = Wv_hi; ga.Wlo[2] = Wv_lo; ga.bias[2] = bv_i;
        ga.X0[0][0] = xa; ga.X0[0][1] = xb;
        ga.X0[1][0] = sa; ga.X0[1][1] = sb;
        ga.X0[2][0] = sa; ga.X0[2][1] = sb;
        ga.out[0][0] = qb; ga.out[0][1] = qb + TEN;
        ga.out[1][0] = kb; ga.out[1][1] = kb + TEN;
        ga.out[2][0] = vb; ga.out[2][1] = vb + TEN;
        ga.X1[0] = ga.X1[1] = nullptr;
        ga.res[0] = ga.res[1] = nullptr;
        ga.M = 256; ga.K = 256; ga.K0 = 256; ga.use_bn = 0; ga.mtiles = 4;
        gemm_tc<<<dim3(32, 12, 2), 128, GEMM_SMEM>>>(ga);

        // attention
        attn_kernel<<<dim3(16, 8, 2), 256, ATTN_SMEM>>>();

        // msg projection
        ga.Whi[0] = Wm_hi; ga.Wlo[0] = Wm_lo; ga.bias[0] = bm_i;
        ga.X0[0][0] = msgb; ga.X0[0][1] = msgb + TEN;
        ga.out[0][0] = mmb; ga.out[0][1] = mmb + TEN;
        ga.M = 256; ga.K = 256; ga.K0 = 256; ga.use_bn = 0; ga.mtiles = 4;
        gemm_tc<<<dim3(32, 4, 2), 128, GEMM_SMEM>>>(ga);

        // h = W1 [x; msg] + b1
        ga.Whi[0] = W1_hi; ga.Wlo[0] = W1_lo; ga.bias[0] = b1_i;
        ga.X0[0][0] = xa; ga.X0[0][1] = xb;
        ga.X1[0] = mmb; ga.X1[1] = mmb + TEN;
        ga.out[0][0] = hb; ga.out[0][1] = hb + HTEN;
        ga.M = 512; ga.K = 512; ga.K0 = 256; ga.use_bn = 0; ga.mtiles = 8;
        gemm_tc<<<dim3(32, 8, 2), 128, GEMM_SMEM>>>(ga);

        // BN stats
        bn_stats_kernel<<<dim3(512, 2), 256>>>(g1_i, be_i);

        // out = res + W2 relu(BN(h)) + b2
        ga.Whi[0] = W2_hi; ga.Wlo[0] = W2_lo; ga.bias[0] = b2_i;
        ga.X0[0][0] = hb; ga.X0[0][1] = hb + HTEN;
        ga.X1[0] = ga.X1[1] = nullptr;
        ga.res[0] = ra; ga.res[1] = rb;
        ga.out[0][0] = oa; ga.out[0][1] = ob;
        ga.M = 256; ga.K = 512; ga.K0 = 512; ga.use_bn = 1; ga.mtiles = 4;
        gemm_tc<<<dim3(32, 4, 2), 128, GEMM_SMEM>>>(ga);
        ga.res[0] = ga.res[1] = nullptr;

        xa = oa; xb = ob;
    }
}